// round 6
// baseline (speedup 1.0000x reference)
#include <cuda_runtime.h>
#include <cstdint>

#define NMAX 100000
#define EMAX 1600000

// Scratch (allocation-free rule: __device__ globals). All atomics target
// these symbols ONLY. Host code never references these symbols.
__device__ float g_H1[(size_t)NMAX * 128];   // x @ W1
__device__ float g_hid[(size_t)NMAX * 128];  // aggregated + relu hidden
__device__ float g_H2[(size_t)NMAX * 40];    // hidden @ W2
__device__ float g_L[(size_t)NMAX * 40];     // aggregated logits (pre-bias)
__device__ float g_dinv[NMAX];
__device__ int   g_deg[NMAX];

// ---------------------------------------------------------------------------
// Degree / normalization  (edge indices are int32!)
// ---------------------------------------------------------------------------
__global__ void k_deg_init(int n) {
    int i = blockIdx.x * blockDim.x + threadIdx.x;
    if (i < n) g_deg[i] = 1;  // self-loop contributes 1
}

__global__ void k_deg_count(const int* __restrict__ dst, int E, int n) {
    int e = blockIdx.x * blockDim.x + threadIdx.x;
    if (e < E) {
        int d = dst[e];
        if ((unsigned)d < (unsigned)n) atomicAdd(&g_deg[d], 1);
    }
}

__global__ void k_dinv(int n) {
    int i = blockIdx.x * blockDim.x + threadIdx.x;
    if (i < n) g_dinv[i] = rsqrtf((float)g_deg[i]);
}

// ---------------------------------------------------------------------------
// GEMM1: g_H1[n,128] = X[n,128] @ W1[128,128]
// 256 threads = 8 warps, 8 rows/warp -> 64 rows/block.
// STATIC smem only: K chunked by 32. Ws 16KB + Xs 8KB = 24KB.
// ---------------------------------------------------------------------------
__global__ void k_gemm1(const float* __restrict__ X, const float* __restrict__ W,
                        int n) {
    __shared__ float Ws[32 * 128];  // K-panel of W: [kk][c]
    __shared__ float Xs[64 * 32];   // X tile: [row][kk]
    int tid = threadIdx.x;
    int warp = tid >> 5, lane = tid & 31;
    int rowBase = blockIdx.x * 64;
    int r0 = warp * 8;

    float4 acc[8];
#pragma unroll
    for (int r = 0; r < 8; r++) acc[r] = make_float4(0.f, 0.f, 0.f, 0.f);

    for (int k0 = 0; k0 < 128; k0 += 32) {
        {
            float4* Ws4 = (float4*)Ws;
            const float4* W4 = (const float4*)(W + (size_t)k0 * 128);
            for (int i = tid; i < 1024; i += 256) Ws4[i] = W4[i];
        }
        for (int i = tid; i < 64 * 32; i += 256) {
            int row = i >> 5, kk = i & 31;
            int grow = rowBase + row;
            Xs[i] = (grow < n) ? X[(size_t)grow * 128 + k0 + kk] : 0.f;
        }
        __syncthreads();

        const float4* Wsf4 = (const float4*)Ws;
#pragma unroll 8
        for (int kk = 0; kk < 32; kk++) {
            float4 w = Wsf4[kk * 32 + lane];
#pragma unroll
            for (int r = 0; r < 8; r++) {
                float xv = Xs[(r0 + r) * 32 + kk];
                acc[r].x += xv * w.x;
                acc[r].y += xv * w.y;
                acc[r].z += xv * w.z;
                acc[r].w += xv * w.w;
            }
        }
        __syncthreads();
    }

    float4* H1f4 = (float4*)g_H1;
#pragma unroll
    for (int r = 0; r < 8; r++) {
        int row = rowBase + r0 + r;
        if (row < n) H1f4[(size_t)row * 32 + lane] = acc[r];
    }
}

// ---------------------------------------------------------------------------
// GEMM2: g_H2[n,40] = g_hid[n,128] @ W2[128,40]
// W2 fully resident in smem padded to 48 cols (24KB) + 8KB X panels = 32KB.
// ---------------------------------------------------------------------------
__global__ void k_gemm2(const float* __restrict__ W2, int n) {
    __shared__ float Ws[128 * 48];  // [k][c], cols 40..47 zero
    __shared__ float Xs[64 * 32];   // [row][kk]
    int tid = threadIdx.x;
    int warp = tid >> 5, lane = tid & 31;
    int rowBase = blockIdx.x * 64;
    int r0 = warp * 8;

    for (int i = tid; i < 128 * 48; i += 256) {
        int k = i / 48, c = i - k * 48;
        Ws[i] = (c < 40) ? W2[k * 40 + c] : 0.f;
    }

    float2 acc[8];
#pragma unroll
    for (int r = 0; r < 8; r++) acc[r] = make_float2(0.f, 0.f);

    for (int k0 = 0; k0 < 128; k0 += 32) {
        for (int i = tid; i < 64 * 32; i += 256) {
            int row = i >> 5, kk = i & 31;
            int grow = rowBase + row;
            Xs[i] = (grow < n) ? g_hid[(size_t)grow * 128 + k0 + kk] : 0.f;
        }
        __syncthreads();

        const float2* Wsf2 = (const float2*)Ws;  // 24 float2 per k-row
        int wcol = (lane < 24) ? lane : 0;
#pragma unroll 8
        for (int kk = 0; kk < 32; kk++) {
            float2 w = Wsf2[(k0 + kk) * 24 + wcol];
#pragma unroll
            for (int r = 0; r < 8; r++) {
                float xv = Xs[(r0 + r) * 32 + kk];
                acc[r].x += xv * w.x;
                acc[r].y += xv * w.y;
            }
        }
        __syncthreads();
    }

    int c = lane * 2;
    if (c < 40) {
#pragma unroll
        for (int r = 0; r < 8; r++) {
            int row = rowBase + r0 + r;
            if (row < n) {
                float2* p = (float2*)(g_H2 + (size_t)row * 40 + c);
                *p = acc[r];
            }
        }
    }
}

// ---------------------------------------------------------------------------
// Self-loop init of the aggregation buffers (device scratch)
// ---------------------------------------------------------------------------
__global__ void k_self1(int n) {
    int i = blockIdx.x * blockDim.x + threadIdx.x;  // over n*32 float4
    if (i < n * 32) {
        int row = i >> 5;
        float s = g_dinv[row]; s *= s;
        float4 v = ((const float4*)g_H1)[i];
        v.x *= s; v.y *= s; v.z *= s; v.w *= s;
        ((float4*)g_hid)[i] = v;
    }
}

__global__ void k_self2(int n) {
    int i = blockIdx.x * blockDim.x + threadIdx.x;  // over n*10 float4
    if (i < n * 10) {
        int row = i / 10;
        float s = g_dinv[row]; s *= s;
        float4 v = ((const float4*)g_H2)[i];
        v.x *= s; v.y *= s; v.z *= s; v.w *= s;
        ((float4*)g_L)[i] = v;
    }
}

// ---------------------------------------------------------------------------
// Edge scatter, layer 1: one warp per edge; lane covers columns
// {lane, lane+32, lane+64, lane+96} -> fully coalesced loads and atomics.
// ---------------------------------------------------------------------------
__global__ void k_scat1(const int* __restrict__ src,
                        const int* __restrict__ dst, int E, int n) {
    int t = blockIdx.x * blockDim.x + threadIdx.x;
    int e = t >> 5, lane = t & 31;
    if (e >= E) return;
    int s = src[e], d = dst[e];
    if ((unsigned)s >= (unsigned)n || (unsigned)d >= (unsigned)n) return;
    float nrm = g_dinv[s] * g_dinv[d];
    const float* hrow = g_H1 + (size_t)s * 128;
    float* orow = g_hid + (size_t)d * 128;
#pragma unroll
    for (int j = 0; j < 4; j++) {
        int c = lane + j * 32;
        atomicAdd(orow + c, hrow[c] * nrm);
    }
}

// ---------------------------------------------------------------------------
// Edge scatter, layer 2: one thread per (edge, column). 40 threads/edge.
// ---------------------------------------------------------------------------
__global__ void k_scat2(const int* __restrict__ src,
                        const int* __restrict__ dst, int E, int n) {
    long long t = (long long)blockIdx.x * blockDim.x + threadIdx.x;
    if (t >= (long long)E * 40) return;
    int e = (int)(t / 40), c = (int)(t - (long long)e * 40);
    int s = src[e], d = dst[e];
    if ((unsigned)s >= (unsigned)n || (unsigned)d >= (unsigned)n) return;
    float nrm = g_dinv[s] * g_dinv[d];
    atomicAdd(g_L + (size_t)d * 40 + c, g_H2[(size_t)s * 40 + c] * nrm);
}

// ---------------------------------------------------------------------------
// Epilogue 1: hidden = relu(agg + b1), in scratch (GEMM2 re-reads it)
// ---------------------------------------------------------------------------
__global__ void k_epi1(const float* __restrict__ b, int n) {
    int i = blockIdx.x * blockDim.x + threadIdx.x;  // over n*32 float4
    if (i < n * 32) {
        float4 bv = ((const float4*)b)[i & 31];
        float4 v = ((float4*)g_hid)[i];
        v.x = fmaxf(v.x + bv.x, 0.f);
        v.y = fmaxf(v.y + bv.y, 0.f);
        v.z = fmaxf(v.z + bv.z, 0.f);
        v.w = fmaxf(v.w + bv.w, 0.f);
        ((float4*)g_hid)[i] = v;
    }
}

// ---------------------------------------------------------------------------
// Final outputs: plain coalesced stores are the ONLY accesses to d_out.
// ---------------------------------------------------------------------------
__global__ void k_out_hidden(float* __restrict__ out, int n) {
    int i = blockIdx.x * blockDim.x + threadIdx.x;  // over n*32 float4
    if (i < n * 32) ((float4*)out)[i] = ((const float4*)g_hid)[i];
}

__global__ void k_out_logits(float* __restrict__ out, const float* __restrict__ b,
                             int n) {
    int i = blockIdx.x * blockDim.x + threadIdx.x;  // over n*10 float4
    if (i < n * 10) {
        int c = i % 10;
        float4 bv = ((const float4*)b)[c];
        float4 v = ((const float4*)g_L)[i];
        v.x += bv.x; v.y += bv.y; v.z += bv.z; v.w += bv.w;
        ((float4*)out)[i] = v;
    }
}

// ---------------------------------------------------------------------------
extern "C" void kernel_launch(void* const* d_in, const int* in_sizes, int n_in,
                              void* d_out, int out_size) {
    (void)n_in; (void)out_size;
    const float* x  = (const float*)d_in[0];
    const int*   ei = (const int*)d_in[1];     // int32 edge index!
    const float* W1 = (const float*)d_in[2];
    const float* b1 = (const float*)d_in[3];
    const float* W2 = (const float*)d_in[4];
    const float* b2 = (const float*)d_in[5];

    int n = in_sizes[0] / 128;
    int E = in_sizes[1] / 2;
    const int* src = ei;
    const int* dst = ei + E;

    float* logits = (float*)d_out;                    // [n, 40]
    float* hidden = logits + (size_t)n * 40;          // [n, 128]

    const int B = 256;

    // Degree + norm
    k_deg_init<<<(n + B - 1) / B, B>>>(n);
    k_deg_count<<<(E + B - 1) / B, B>>>(dst, E, n);
    k_dinv<<<(n + B - 1) / B, B>>>(n);

    // Layer 1
    k_gemm1<<<(n + 63) / 64, B>>>(x, W1, n);
    k_self1<<<(n * 32 + B - 1) / B, B>>>(n);
    {
        long long threads = (long long)E * 32;
        k_scat1<<<(int)((threads + B - 1) / B), B>>>(src, dst, E, n);
    }
    k_epi1<<<(n * 32 + B - 1) / B, B>>>(b1, n);

    // Layer 2
    k_gemm2<<<(n + 63) / 64, B>>>(W2, n);
    k_self2<<<(n * 10 + B - 1) / B, B>>>(n);
    {
        long long threads = (long long)E * 40;
        k_scat2<<<(int)((threads + B - 1) / B), B>>>(src, dst, E, n);
    }

    // Outputs (plain stores only)
    k_out_hidden<<<(n * 32 + B - 1) / B, B>>>(hidden, n);
    k_out_logits<<<(n * 10 + B - 1) / B, B>>>(logits, b2, n);
}

// round 7
// speedup vs baseline: 1.5001x; 1.5001x over previous
#include <cuda_runtime.h>
#include <cstdint>

#define NMAX 100000
#define EMAX 1600000

// Scratch (allocation-free rule: __device__ globals). All atomics target
// these symbols ONLY. Host code never references these symbols.
__device__ float g_H1[(size_t)NMAX * 128];   // x @ W1
__device__ float g_hid[(size_t)NMAX * 128];  // aggregated + relu hidden
__device__ float g_H2[(size_t)NMAX * 40];    // hidden @ W2
__device__ float g_L[(size_t)NMAX * 40];     // aggregated logits (pre-bias)
__device__ float g_dinv[NMAX];
__device__ int   g_deg[NMAX];

// Vector atomic add (sm_90+): one 16B RED per lane.
__device__ __forceinline__ void red_add_v4(float* p, float4 v) {
    asm volatile("red.global.add.v4.f32 [%0], {%1,%2,%3,%4};"
                 :: "l"(p), "f"(v.x), "f"(v.y), "f"(v.z), "f"(v.w)
                 : "memory");
}

// ---------------------------------------------------------------------------
// Degree / normalization  (edge indices are int32)
// ---------------------------------------------------------------------------
__global__ void k_deg_init(int n) {
    int i = blockIdx.x * blockDim.x + threadIdx.x;
    if (i < n) g_deg[i] = 1;  // self-loop contributes 1
}

__global__ void k_deg_count(const int* __restrict__ dst, int E, int n) {
    int e = blockIdx.x * blockDim.x + threadIdx.x;
    if (e < E) {
        int d = dst[e];
        if ((unsigned)d < (unsigned)n) atomicAdd(&g_deg[d], 1);
    }
}

__global__ void k_dinv(int n) {
    int i = blockIdx.x * blockDim.x + threadIdx.x;
    if (i < n) g_dinv[i] = rsqrtf((float)g_deg[i]);
}

// ---------------------------------------------------------------------------
// GEMM1: g_H1[n,128] = X @ W1; fused self-loop: g_hid = H1 * dinv^2
// 256 threads = 8 warps, 8 rows/warp -> 64 rows/block. Static smem 24KB.
// ---------------------------------------------------------------------------
__global__ void k_gemm1(const float* __restrict__ X, const float* __restrict__ W,
                        int n) {
    __shared__ float Ws[32 * 128];  // K-panel of W: [kk][c]
    __shared__ float Xs[64 * 32];   // X tile: [row][kk]
    int tid = threadIdx.x;
    int warp = tid >> 5, lane = tid & 31;
    int rowBase = blockIdx.x * 64;
    int r0 = warp * 8;

    float4 acc[8];
#pragma unroll
    for (int r = 0; r < 8; r++) acc[r] = make_float4(0.f, 0.f, 0.f, 0.f);

    for (int k0 = 0; k0 < 128; k0 += 32) {
        {
            float4* Ws4 = (float4*)Ws;
            const float4* W4 = (const float4*)(W + (size_t)k0 * 128);
            for (int i = tid; i < 1024; i += 256) Ws4[i] = W4[i];
        }
        for (int i = tid; i < 64 * 32; i += 256) {
            int row = i >> 5, kk = i & 31;
            int grow = rowBase + row;
            Xs[i] = (grow < n) ? X[(size_t)grow * 128 + k0 + kk] : 0.f;
        }
        __syncthreads();

        const float4* Wsf4 = (const float4*)Ws;
#pragma unroll 8
        for (int kk = 0; kk < 32; kk++) {
            float4 w = Wsf4[kk * 32 + lane];
#pragma unroll
            for (int r = 0; r < 8; r++) {
                float xv = Xs[(r0 + r) * 32 + kk];
                acc[r].x += xv * w.x;
                acc[r].y += xv * w.y;
                acc[r].z += xv * w.z;
                acc[r].w += xv * w.w;
            }
        }
        __syncthreads();
    }

    float4* H1f4 = (float4*)g_H1;
    float4* Hidf4 = (float4*)g_hid;
#pragma unroll
    for (int r = 0; r < 8; r++) {
        int row = rowBase + r0 + r;
        if (row < n) {
            size_t idx = (size_t)row * 32 + lane;
            H1f4[idx] = acc[r];
            float s = g_dinv[row]; s *= s;
            float4 v = acc[r];
            v.x *= s; v.y *= s; v.z *= s; v.w *= s;
            Hidf4[idx] = v;
        }
    }
}

// ---------------------------------------------------------------------------
// GEMM2: g_H2[n,40] = g_hid @ W2; fused self-loop: g_L = H2 * dinv^2
// W2 resident in smem padded to 48 cols (24KB) + 8KB X panels.
// ---------------------------------------------------------------------------
__global__ void k_gemm2(const float* __restrict__ W2, int n) {
    __shared__ float Ws[128 * 48];  // [k][c], cols 40..47 zero
    __shared__ float Xs[64 * 32];   // [row][kk]
    int tid = threadIdx.x;
    int warp = tid >> 5, lane = tid & 31;
    int rowBase = blockIdx.x * 64;
    int r0 = warp * 8;

    for (int i = tid; i < 128 * 48; i += 256) {
        int k = i / 48, c = i - k * 48;
        Ws[i] = (c < 40) ? W2[k * 40 + c] : 0.f;
    }

    float2 acc[8];
#pragma unroll
    for (int r = 0; r < 8; r++) acc[r] = make_float2(0.f, 0.f);

    for (int k0 = 0; k0 < 128; k0 += 32) {
        for (int i = tid; i < 64 * 32; i += 256) {
            int row = i >> 5, kk = i & 31;
            int grow = rowBase + row;
            Xs[i] = (grow < n) ? g_hid[(size_t)grow * 128 + k0 + kk] : 0.f;
        }
        __syncthreads();

        const float2* Wsf2 = (const float2*)Ws;  // 24 float2 per k-row
        int wcol = (lane < 24) ? lane : 0;
#pragma unroll 8
        for (int kk = 0; kk < 32; kk++) {
            float2 w = Wsf2[(k0 + kk) * 24 + wcol];
#pragma unroll
            for (int r = 0; r < 8; r++) {
                float xv = Xs[(r0 + r) * 32 + kk];
                acc[r].x += xv * w.x;
                acc[r].y += xv * w.y;
            }
        }
        __syncthreads();
    }

    int c = lane * 2;
    if (c < 40) {
#pragma unroll
        for (int r = 0; r < 8; r++) {
            int row = rowBase + r0 + r;
            if (row < n) {
                float2 a = acc[r];
                *(float2*)(g_H2 + (size_t)row * 40 + c) = a;
                float s = g_dinv[row]; s *= s;
                a.x *= s; a.y *= s;
                *(float2*)(g_L + (size_t)row * 40 + c) = a;
            }
        }
    }
}

// ---------------------------------------------------------------------------
// Edge scatter, layer 1: one warp per edge; lane covers columns
// [4*lane, 4*lane+4) -> one coalesced 512B gather + one v4 RED per lane.
// ---------------------------------------------------------------------------
__global__ void k_scat1(const int* __restrict__ src,
                        const int* __restrict__ dst, int E, int n) {
    int t = blockIdx.x * blockDim.x + threadIdx.x;
    int e = t >> 5, lane = t & 31;
    if (e >= E) return;
    int s = src[e], d = dst[e];
    if ((unsigned)s >= (unsigned)n || (unsigned)d >= (unsigned)n) return;
    float nrm = g_dinv[s] * g_dinv[d];
    float4 v = ((const float4*)g_H1)[(size_t)s * 32 + lane];
    v.x *= nrm; v.y *= nrm; v.z *= nrm; v.w *= nrm;
    red_add_v4(g_hid + (size_t)d * 128 + lane * 4, v);
}

// ---------------------------------------------------------------------------
// Edge scatter, layer 2: one thread per (edge, float4 chunk). 10 chunks/edge.
// ---------------------------------------------------------------------------
__global__ void k_scat2(const int* __restrict__ src,
                        const int* __restrict__ dst, int E, int n) {
    long long t = (long long)blockIdx.x * blockDim.x + threadIdx.x;
    if (t >= (long long)E * 10) return;
    int e = (int)(t / 10), c = (int)(t - (long long)e * 10);
    int s = src[e], d = dst[e];
    if ((unsigned)s >= (unsigned)n || (unsigned)d >= (unsigned)n) return;
    float nrm = g_dinv[s] * g_dinv[d];
    float4 v = ((const float4*)g_H2)[(size_t)s * 10 + c];
    v.x *= nrm; v.y *= nrm; v.z *= nrm; v.w *= nrm;
    red_add_v4(g_L + (size_t)d * 40 + c * 4, v);
}

// ---------------------------------------------------------------------------
// Epilogue 1: hidden = relu(agg + b1) -> writes BOTH scratch and d_out.
// ---------------------------------------------------------------------------
__global__ void k_epi1(float* __restrict__ out, const float* __restrict__ b,
                       int n) {
    int i = blockIdx.x * blockDim.x + threadIdx.x;  // over n*32 float4
    if (i < n * 32) {
        float4 bv = ((const float4*)b)[i & 31];
        float4 v = ((float4*)g_hid)[i];
        v.x = fmaxf(v.x + bv.x, 0.f);
        v.y = fmaxf(v.y + bv.y, 0.f);
        v.z = fmaxf(v.z + bv.z, 0.f);
        v.w = fmaxf(v.w + bv.w, 0.f);
        ((float4*)g_hid)[i] = v;
        ((float4*)out)[i] = v;
    }
}

// ---------------------------------------------------------------------------
// Final logits: g_L + b2 -> d_out (plain stores only)
// ---------------------------------------------------------------------------
__global__ void k_out_logits(float* __restrict__ out, const float* __restrict__ b,
                             int n) {
    int i = blockIdx.x * blockDim.x + threadIdx.x;  // over n*10 float4
    if (i < n * 10) {
        int c = i % 10;
        float4 bv = ((const float4*)b)[c];
        float4 v = ((const float4*)g_L)[i];
        v.x += bv.x; v.y += bv.y; v.z += bv.z; v.w += bv.w;
        ((float4*)out)[i] = v;
    }
}

// ---------------------------------------------------------------------------
extern "C" void kernel_launch(void* const* d_in, const int* in_sizes, int n_in,
                              void* d_out, int out_size) {
    (void)n_in; (void)out_size;
    const float* x  = (const float*)d_in[0];
    const int*   ei = (const int*)d_in[1];     // int32 edge index
    const float* W1 = (const float*)d_in[2];
    const float* b1 = (const float*)d_in[3];
    const float* W2 = (const float*)d_in[4];
    const float* b2 = (const float*)d_in[5];

    int n = in_sizes[0] / 128;
    int E = in_sizes[1] / 2;
    const int* src = ei;
    const int* dst = ei + E;

    float* logits = (float*)d_out;                    // [n, 40]
    float* hidden = logits + (size_t)n * 40;          // [n, 128]

    const int B = 256;

    // Degree + norm
    k_deg_init<<<(n + B - 1) / B, B>>>(n);
    k_deg_count<<<(E + B - 1) / B, B>>>(dst, E, n);
    k_dinv<<<(n + B - 1) / B, B>>>(n);

    // Layer 1 (gemm1 fuses self-loop init of g_hid)
    k_gemm1<<<(n + 63) / 64, B>>>(x, W1, n);
    {
        long long threads = (long long)E * 32;
        k_scat1<<<(int)((threads + B - 1) / B), B>>>(src, dst, E, n);
    }
    k_epi1<<<(n * 32 + B - 1) / B, B>>>(hidden, b1, n);

    // Layer 2 (gemm2 fuses self-loop init of g_L)
    k_gemm2<<<(n + 63) / 64, B>>>(W2, n);
    {
        long long threads = (long long)E * 10;
        k_scat2<<<(int)((threads + B - 1) / B), B>>>(src, dst, E, n);
    }
    k_out_logits<<<(n * 10 + B - 1) / B, B>>>(logits, b2, n);
}

// round 9
// speedup vs baseline: 2.1567x; 1.4377x over previous
#include <cuda_runtime.h>
#include <cstdint>

#define NMAX 100000
#define EMAX 1600000
#define SCAN_B 1024
#define MAXBLK 128   // >= ceil(NMAX/SCAN_B) = 98

// Scratch (allocation-free rule: __device__ globals).
__device__ float g_H1[(size_t)NMAX * 128];   // x @ W1
__device__ float g_hid[(size_t)NMAX * 128];  // relu(agg1 + b1)
__device__ float g_H2[(size_t)NMAX * 40];    // hidden @ W2
__device__ float g_dinv[NMAX];
__device__ int   g_deg[NMAX];                // in-degree + 1 (self loop)
__device__ int   g_off[NMAX + 1];            // CSR row offsets (by dst)
__device__ int   g_pos[NMAX];                // bucket cursors
__device__ int   g_esrc[EMAX];               // src id per CSR slot
__device__ int   g_part[MAXBLK];             // scan partials
__device__ int   g_partx[MAXBLK];            // exclusive-scanned partials

// ---------------------------------------------------------------------------
// Degree / normalization  (edge indices are int32)
// ---------------------------------------------------------------------------
__global__ void k_deg_init(int n) {
    int i = blockIdx.x * blockDim.x + threadIdx.x;
    if (i < n) g_deg[i] = 1;  // self-loop
}

__global__ void k_deg_count(const int* __restrict__ dst, int E, int n) {
    int e = blockIdx.x * blockDim.x + threadIdx.x;
    if (e < E) {
        int d = dst[e];
        if ((unsigned)d < (unsigned)n) atomicAdd(&g_deg[d], 1);
    }
}

__global__ void k_dinv(int n) {
    int i = blockIdx.x * blockDim.x + threadIdx.x;
    if (i < n) g_dinv[i] = rsqrtf((float)g_deg[i]);
}

// ---------------------------------------------------------------------------
// CSR build: exclusive scan of edge counts (deg-1), then bucket scatter.
// ---------------------------------------------------------------------------
__global__ void k_scan1(int n) {
    __shared__ int sh[SCAN_B];
    int tid = threadIdx.x;
    int i = blockIdx.x * SCAN_B + tid;
    int v = (i < n) ? (g_deg[i] - 1) : 0;
    sh[tid] = v;
    __syncthreads();
    for (int off = 1; off < SCAN_B; off <<= 1) {
        int t = (tid >= off) ? sh[tid - off] : 0;
        __syncthreads();
        sh[tid] += t;
        __syncthreads();
    }
    if (i < n) g_off[i] = sh[tid] - v;       // block-local exclusive
    if (tid == SCAN_B - 1) g_part[blockIdx.x] = sh[tid];
}

__global__ void k_scan2(int nblocks) {
    __shared__ int sh[MAXBLK];
    int tid = threadIdx.x;
    int v = (tid < nblocks) ? g_part[tid] : 0;
    sh[tid] = v;
    __syncthreads();
    for (int off = 1; off < MAXBLK; off <<= 1) {
        int t = (tid >= off) ? sh[tid - off] : 0;
        __syncthreads();
        sh[tid] += t;
        __syncthreads();
    }
    if (tid < nblocks) g_partx[tid] = sh[tid] - v;  // exclusive
}

__global__ void k_scan3(int n, int E) {
    int i = blockIdx.x * blockDim.x + threadIdx.x;
    if (i < n) {
        int o = g_off[i] + g_partx[i / SCAN_B];
        g_off[i] = o;
        g_pos[i] = o;
    }
    if (i == 0) g_off[n] = E;
}

__global__ void k_bucket(const int* __restrict__ src,
                         const int* __restrict__ dst, int E, int n) {
    int e = blockIdx.x * blockDim.x + threadIdx.x;
    if (e >= E) return;
    int s = src[e], d = dst[e];
    if ((unsigned)s >= (unsigned)n || (unsigned)d >= (unsigned)n) return;
    int p = atomicAdd(&g_pos[d], 1);
    g_esrc[p] = s;
}

// ---------------------------------------------------------------------------
// GEMM1: g_H1[n,128] = X @ W1. Static smem 24KB, 8 warps, 8 rows/warp.
// ---------------------------------------------------------------------------
__global__ void k_gemm1(const float* __restrict__ X, const float* __restrict__ W,
                        int n) {
    __shared__ float Ws[32 * 128];
    __shared__ float Xs[64 * 32];
    int tid = threadIdx.x;
    int warp = tid >> 5, lane = tid & 31;
    int rowBase = blockIdx.x * 64;
    int r0 = warp * 8;

    float4 acc[8];
#pragma unroll
    for (int r = 0; r < 8; r++) acc[r] = make_float4(0.f, 0.f, 0.f, 0.f);

    for (int k0 = 0; k0 < 128; k0 += 32) {
        {
            float4* Ws4 = (float4*)Ws;
            const float4* W4 = (const float4*)(W + (size_t)k0 * 128);
            for (int i = tid; i < 1024; i += 256) Ws4[i] = W4[i];
        }
        for (int i = tid; i < 64 * 32; i += 256) {
            int row = i >> 5, kk = i & 31;
            int grow = rowBase + row;
            Xs[i] = (grow < n) ? X[(size_t)grow * 128 + k0 + kk] : 0.f;
        }
        __syncthreads();

        const float4* Wsf4 = (const float4*)Ws;
#pragma unroll 8
        for (int kk = 0; kk < 32; kk++) {
            float4 w = Wsf4[kk * 32 + lane];
#pragma unroll
            for (int r = 0; r < 8; r++) {
                float xv = Xs[(r0 + r) * 32 + kk];
                acc[r].x += xv * w.x;
                acc[r].y += xv * w.y;
                acc[r].z += xv * w.z;
                acc[r].w += xv * w.w;
            }
        }
        __syncthreads();
    }

    float4* H1f4 = (float4*)g_H1;
#pragma unroll
    for (int r = 0; r < 8; r++) {
        int row = rowBase + r0 + r;
        if (row < n) H1f4[(size_t)row * 32 + lane] = acc[r];
    }
}

// ---------------------------------------------------------------------------
// GEMM2: g_H2[n,40] = g_hid @ W2.
// ---------------------------------------------------------------------------
__global__ void k_gemm2(const float* __restrict__ W2, int n) {
    __shared__ float Ws[128 * 48];
    __shared__ float Xs[64 * 32];
    int tid = threadIdx.x;
    int warp = tid >> 5, lane = tid & 31;
    int rowBase = blockIdx.x * 64;
    int r0 = warp * 8;

    for (int i = tid; i < 128 * 48; i += 256) {
        int k = i / 48, c = i - k * 48;
        Ws[i] = (c < 40) ? W2[k * 40 + c] : 0.f;
    }

    float2 acc[8];
#pragma unroll
    for (int r = 0; r < 8; r++) acc[r] = make_float2(0.f, 0.f);

    for (int k0 = 0; k0 < 128; k0 += 32) {
        for (int i = tid; i < 64 * 32; i += 256) {
            int row = i >> 5, kk = i & 31;
            int grow = rowBase + row;
            Xs[i] = (grow < n) ? g_hid[(size_t)grow * 128 + k0 + kk] : 0.f;
        }
        __syncthreads();

        const float2* Wsf2 = (const float2*)Ws;
        int wcol = (lane < 24) ? lane : 0;
#pragma unroll 8
        for (int kk = 0; kk < 32; kk++) {
            float2 w = Wsf2[(k0 + kk) * 24 + wcol];
#pragma unroll
            for (int r = 0; r < 8; r++) {
                float xv = Xs[(r0 + r) * 32 + kk];
                acc[r].x += xv * w.x;
                acc[r].y += xv * w.y;
            }
        }
        __syncthreads();
    }

    int c = lane * 2;
    if (c < 40) {
#pragma unroll
        for (int r = 0; r < 8; r++) {
            int row = rowBase + r0 + r;
            if (row < n) *(float2*)(g_H2 + (size_t)row * 40 + c) = acc[r];
        }
    }
}

// ---------------------------------------------------------------------------
// Gather layer 1: warp per dst node. acc = dinv^2*H1[d] + sum_e nrm*H1[src]
// then relu(acc + b1) -> g_hid and d_out hidden. No atomics.
// ---------------------------------------------------------------------------
__global__ void k_gather1(const float* __restrict__ b1, float* __restrict__ out,
                          int n) {
    int w = (blockIdx.x * blockDim.x + threadIdx.x) >> 5;
    int lane = threadIdx.x & 31;
    if (w >= n) return;
    int d = w;
    float dd = g_dinv[d];
    const float4* H1 = (const float4*)g_H1;

    float4 acc = H1[(size_t)d * 32 + lane];
    float sl = dd * dd;
    acc.x *= sl; acc.y *= sl; acc.z *= sl; acc.w *= sl;

    int start = g_off[d], end = g_off[d + 1];
    for (int base = start; base < end; base += 32) {
        int idx = base + lane;
        int sv = (idx < end) ? g_esrc[idx] : 0;
        int cnt = end - base; if (cnt > 32) cnt = 32;
        for (int j = 0; j < cnt; j++) {
            int s = __shfl_sync(0xffffffffu, sv, j);
            float nrm = g_dinv[s] * dd;
            float4 v = H1[(size_t)s * 32 + lane];
            acc.x += v.x * nrm;
            acc.y += v.y * nrm;
            acc.z += v.z * nrm;
            acc.w += v.w * nrm;
        }
    }

    float4 bv = ((const float4*)b1)[lane];
    acc.x = fmaxf(acc.x + bv.x, 0.f);
    acc.y = fmaxf(acc.y + bv.y, 0.f);
    acc.z = fmaxf(acc.z + bv.z, 0.f);
    acc.w = fmaxf(acc.w + bv.w, 0.f);

    size_t idx4 = (size_t)d * 32 + lane;
    ((float4*)g_hid)[idx4] = acc;
    ((float4*)out)[idx4] = acc;
}

// ---------------------------------------------------------------------------
// Gather layer 2: warp per dst node; lanes 0..19 hold one float2 (40 cols).
// logits = agg + b2 -> d_out directly. No atomics.
// ---------------------------------------------------------------------------
__global__ void k_gather2(const float* __restrict__ b2, float* __restrict__ out,
                          int n) {
    int w = (blockIdx.x * blockDim.x + threadIdx.x) >> 5;
    int lane = threadIdx.x & 31;
    if (w >= n) return;
    int d = w;
    bool act = lane < 20;
    float dd = g_dinv[d];
    const float2* H2 = (const float2*)g_H2;

    float2 acc = make_float2(0.f, 0.f);
    if (act) {
        acc = H2[(size_t)d * 20 + lane];
        float sl = dd * dd;
        acc.x *= sl; acc.y *= sl;
    }

    int start = g_off[d], end = g_off[d + 1];
    for (int base = start; base < end; base += 32) {
        int idx = base + lane;
        int sv = (idx < end) ? g_esrc[idx] : 0;
        int cnt = end - base; if (cnt > 32) cnt = 32;
        for (int j = 0; j < cnt; j++) {
            int s = __shfl_sync(0xffffffffu, sv, j);
            if (act) {
                float nrm = g_dinv[s] * dd;
                float2 v = H2[(size_t)s * 20 + lane];
                acc.x += v.x * nrm;
                acc.y += v.y * nrm;
            }
        }
    }

    if (act) {
        float2 bv = ((const float2*)b2)[lane];
        acc.x += bv.x; acc.y += bv.y;
        ((float2*)out)[(size_t)d * 20 + lane] = acc;
    }
}

// ---------------------------------------------------------------------------
extern "C" void kernel_launch(void* const* d_in, const int* in_sizes, int n_in,
                              void* d_out, int out_size) {
    (void)n_in; (void)out_size;
    const float* x  = (const float*)d_in[0];
    const int*   ei = (const int*)d_in[1];     // int32 edge index
    const float* W1 = (const float*)d_in[2];
    const float* b1 = (const float*)d_in[3];
    const float* W2 = (const float*)d_in[4];
    const float* b2 = (const float*)d_in[5];

    int n = in_sizes[0] / 128;
    int E = in_sizes[1] / 2;
    const int* src = ei;
    const int* dst = ei + E;

    float* logits = (float*)d_out;                    // [n, 40]
    float* hidden = logits + (size_t)n * 40;          // [n, 128]

    const int B = 256;
    int nscan = (n + SCAN_B - 1) / SCAN_B;

    // Degree + norm
    k_deg_init<<<(n + B - 1) / B, B>>>(n);
    k_deg_count<<<(E + B - 1) / B, B>>>(dst, E, n);
    k_dinv<<<(n + B - 1) / B, B>>>(n);

    // CSR build (by dst)
    k_scan1<<<nscan, SCAN_B>>>(n);
    k_scan2<<<1, MAXBLK>>>(nscan);
    k_scan3<<<(n + B - 1) / B, B>>>(n, E);
    k_bucket<<<(E + B - 1) / B, B>>>(src, dst, E, n);

    // Layer 1: GEMM then gather (fused bias+relu+output)
    k_gemm1<<<(n + 63) / 64, B>>>(x, W1, n);
    k_gather1<<<(n * 32 + B - 1) / B, B>>>(b1, hidden, n);

    // Layer 2: GEMM then gather (fused bias+output)
    k_gemm2<<<(n + 63) / 64, B>>>(W2, n);
    k_gather2<<<(n * 32 + B - 1) / B, B>>>(b2, logits, n);
}

// round 10
// speedup vs baseline: 2.3022x; 1.0675x over previous
#include <cuda_runtime.h>
#include <cstdint>

#define NMAX 100000
#define EMAX 1600000
#define SCAN_B 1024
#define MAXBLK 128   // >= ceil(NMAX/SCAN_B) = 98

// Scratch (allocation-free rule: __device__ globals).
__device__ float g_H1[(size_t)NMAX * 128];   // x @ W1
__device__ float g_hid[(size_t)NMAX * 128];  // relu(agg1 + b1)
__device__ float g_H2[(size_t)NMAX * 40];    // hidden @ W2
__device__ float g_dinv[NMAX];
__device__ int   g_deg[NMAX];                // in-degree + 1 (self loop)
__device__ int   g_off[NMAX + 1];            // CSR row offsets (by dst)
__device__ int   g_pos[NMAX];                // bucket cursors
__device__ int   g_esrc[EMAX];               // src id per CSR slot
__device__ float g_enrm[EMAX];               // dinv[s]*dinv[d] per CSR slot
__device__ int   g_part[MAXBLK];             // scan partials
__device__ int   g_partx[MAXBLK];            // exclusive-scanned partials

// ---------------------------------------------------------------------------
// Degree / normalization  (edge indices are int32)
// ---------------------------------------------------------------------------
__global__ void k_deg_init(int n) {
    int i = blockIdx.x * blockDim.x + threadIdx.x;
    if (i < n) g_deg[i] = 1;  // self-loop
}

__global__ void k_deg_count(const int* __restrict__ dst, int E, int n) {
    int e = blockIdx.x * blockDim.x + threadIdx.x;
    if (e < E) {
        int d = dst[e];
        if ((unsigned)d < (unsigned)n) atomicAdd(&g_deg[d], 1);
    }
}

__global__ void k_dinv(int n) {
    int i = blockIdx.x * blockDim.x + threadIdx.x;
    if (i < n) g_dinv[i] = rsqrtf((float)g_deg[i]);
}

// ---------------------------------------------------------------------------
// CSR build: exclusive scan of edge counts (deg-1), then bucket scatter.
// ---------------------------------------------------------------------------
__global__ void k_scan1(int n) {
    __shared__ int sh[SCAN_B];
    int tid = threadIdx.x;
    int i = blockIdx.x * SCAN_B + tid;
    int v = (i < n) ? (g_deg[i] - 1) : 0;
    sh[tid] = v;
    __syncthreads();
    for (int off = 1; off < SCAN_B; off <<= 1) {
        int t = (tid >= off) ? sh[tid - off] : 0;
        __syncthreads();
        sh[tid] += t;
        __syncthreads();
    }
    if (i < n) g_off[i] = sh[tid] - v;       // block-local exclusive
    if (tid == SCAN_B - 1) g_part[blockIdx.x] = sh[tid];
}

__global__ void k_scan2(int nblocks) {
    __shared__ int sh[MAXBLK];
    int tid = threadIdx.x;
    int v = (tid < nblocks) ? g_part[tid] : 0;
    sh[tid] = v;
    __syncthreads();
    for (int off = 1; off < MAXBLK; off <<= 1) {
        int t = (tid >= off) ? sh[tid - off] : 0;
        __syncthreads();
        sh[tid] += t;
        __syncthreads();
    }
    if (tid < nblocks) g_partx[tid] = sh[tid] - v;  // exclusive
}

__global__ void k_scan3(int n, int E) {
    int i = blockIdx.x * blockDim.x + threadIdx.x;
    if (i < n) {
        int o = g_off[i] + g_partx[i / SCAN_B];
        g_off[i] = o;
        g_pos[i] = o;
    }
    if (i == 0) g_off[n] = E;
}

__global__ void k_bucket(const int* __restrict__ src,
                         const int* __restrict__ dst, int E, int n) {
    int e = blockIdx.x * blockDim.x + threadIdx.x;
    if (e >= E) return;
    int s = src[e], d = dst[e];
    if ((unsigned)s >= (unsigned)n || (unsigned)d >= (unsigned)n) return;
    float nrm = g_dinv[s] * g_dinv[d];
    int p = atomicAdd(&g_pos[d], 1);
    g_esrc[p] = s;
    g_enrm[p] = nrm;
}

// ---------------------------------------------------------------------------
// GEMM1: g_H1[n,128] = X @ W1. kk chunked by 4: 4 live w-vectors, xv as
// float4 broadcast LDS -> 96 LDS.128 per panel instead of 288 LDS.
// ---------------------------------------------------------------------------
__global__ void k_gemm1(const float* __restrict__ X, const float* __restrict__ W,
                        int n) {
    __shared__ float Ws[32 * 128];
    __shared__ float Xs[64 * 32];
    int tid = threadIdx.x;
    int warp = tid >> 5, lane = tid & 31;
    int rowBase = blockIdx.x * 64;
    int r0 = warp * 8;

    float4 acc[8];
#pragma unroll
    for (int r = 0; r < 8; r++) acc[r] = make_float4(0.f, 0.f, 0.f, 0.f);

    for (int k0 = 0; k0 < 128; k0 += 32) {
        {
            float4* Ws4 = (float4*)Ws;
            const float4* W4 = (const float4*)(W + (size_t)k0 * 128);
            for (int i = tid; i < 1024; i += 256) Ws4[i] = W4[i];
        }
        for (int i = tid; i < 64 * 32; i += 256) {
            int row = i >> 5, kk = i & 31;
            int grow = rowBase + row;
            Xs[i] = (grow < n) ? X[(size_t)grow * 128 + k0 + kk] : 0.f;
        }
        __syncthreads();

        const float4* Wsf4 = (const float4*)Ws;
#pragma unroll
        for (int kk = 0; kk < 32; kk += 4) {
            float4 w0 = Wsf4[(kk + 0) * 32 + lane];
            float4 w1 = Wsf4[(kk + 1) * 32 + lane];
            float4 w2 = Wsf4[(kk + 2) * 32 + lane];
            float4 w3 = Wsf4[(kk + 3) * 32 + lane];
#pragma unroll
            for (int r = 0; r < 8; r++) {
                float4 xv = *(const float4*)&Xs[(r0 + r) * 32 + kk];
                acc[r].x = fmaf(xv.x, w0.x, acc[r].x);
                acc[r].y = fmaf(xv.x, w0.y, acc[r].y);
                acc[r].z = fmaf(xv.x, w0.z, acc[r].z);
                acc[r].w = fmaf(xv.x, w0.w, acc[r].w);
                acc[r].x = fmaf(xv.y, w1.x, acc[r].x);
                acc[r].y = fmaf(xv.y, w1.y, acc[r].y);
                acc[r].z = fmaf(xv.y, w1.z, acc[r].z);
                acc[r].w = fmaf(xv.y, w1.w, acc[r].w);
                acc[r].x = fmaf(xv.z, w2.x, acc[r].x);
                acc[r].y = fmaf(xv.z, w2.y, acc[r].y);
                acc[r].z = fmaf(xv.z, w2.z, acc[r].z);
                acc[r].w = fmaf(xv.z, w2.w, acc[r].w);
                acc[r].x = fmaf(xv.w, w3.x, acc[r].x);
                acc[r].y = fmaf(xv.w, w3.y, acc[r].y);
                acc[r].z = fmaf(xv.w, w3.z, acc[r].z);
                acc[r].w = fmaf(xv.w, w3.w, acc[r].w);
            }
        }
        __syncthreads();
    }

    float4* H1f4 = (float4*)g_H1;
#pragma unroll
    for (int r = 0; r < 8; r++) {
        int row = rowBase + r0 + r;
        if (row < n) H1f4[(size_t)row * 32 + lane] = acc[r];
    }
}

// ---------------------------------------------------------------------------
// GEMM2: g_H2[n,40] = g_hid @ W2. Same kk-chunked structure.
// ---------------------------------------------------------------------------
__global__ void k_gemm2(const float* __restrict__ W2, int n) {
    __shared__ float Ws[128 * 48];
    __shared__ float Xs[64 * 32];
    int tid = threadIdx.x;
    int warp = tid >> 5, lane = tid & 31;
    int rowBase = blockIdx.x * 64;
    int r0 = warp * 8;

    for (int i = tid; i < 128 * 48; i += 256) {
        int k = i / 48, c = i - k * 48;
        Ws[i] = (c < 40) ? W2[k * 40 + c] : 0.f;
    }

    float2 acc[8];
#pragma unroll
    for (int r = 0; r < 8; r++) acc[r] = make_float2(0.f, 0.f);

    for (int k0 = 0; k0 < 128; k0 += 32) {
        for (int i = tid; i < 64 * 32; i += 256) {
            int row = i >> 5, kk = i & 31;
            int grow = rowBase + row;
            Xs[i] = (grow < n) ? g_hid[(size_t)grow * 128 + k0 + kk] : 0.f;
        }
        __syncthreads();

        const float2* Wsf2 = (const float2*)Ws;
        int wcol = (lane < 24) ? lane : 0;
#pragma unroll
        for (int kk = 0; kk < 32; kk += 4) {
            float2 w0 = Wsf2[(k0 + kk + 0) * 24 + wcol];
            float2 w1 = Wsf2[(k0 + kk + 1) * 24 + wcol];
            float2 w2 = Wsf2[(k0 + kk + 2) * 24 + wcol];
            float2 w3 = Wsf2[(k0 + kk + 3) * 24 + wcol];
#pragma unroll
            for (int r = 0; r < 8; r++) {
                float4 xv = *(const float4*)&Xs[(r0 + r) * 32 + kk];
                acc[r].x = fmaf(xv.x, w0.x, acc[r].x);
                acc[r].y = fmaf(xv.x, w0.y, acc[r].y);
                acc[r].x = fmaf(xv.y, w1.x, acc[r].x);
                acc[r].y = fmaf(xv.y, w1.y, acc[r].y);
                acc[r].x = fmaf(xv.z, w2.x, acc[r].x);
                acc[r].y = fmaf(xv.z, w2.y, acc[r].y);
                acc[r].x = fmaf(xv.w, w3.x, acc[r].x);
                acc[r].y = fmaf(xv.w, w3.y, acc[r].y);
            }
        }
        __syncthreads();
    }

    int c = lane * 2;
    if (c < 40) {
#pragma unroll
        for (int r = 0; r < 8; r++) {
            int row = rowBase + r0 + r;
            if (row < n) *(float2*)(g_H2 + (size_t)row * 40 + c) = acc[r];
        }
    }
}

// ---------------------------------------------------------------------------
// Gather layer 1: warp per dst node, dual accumulators (2 edges per step)
// for 2x memory-level parallelism. nrm precomputed in CSR.
// ---------------------------------------------------------------------------
__global__ void k_gather1(const float* __restrict__ b1, float* __restrict__ out,
                          int n) {
    int w = (blockIdx.x * blockDim.x + threadIdx.x) >> 5;
    int lane = threadIdx.x & 31;
    if (w >= n) return;
    int d = w;
    float dd = g_dinv[d];
    const float4* H1 = (const float4*)g_H1;

    float4 acc = H1[(size_t)d * 32 + lane];
    float sl = dd * dd;
    acc.x *= sl; acc.y *= sl; acc.z *= sl; acc.w *= sl;
    float4 accB = make_float4(0.f, 0.f, 0.f, 0.f);

    int start = g_off[d], end = g_off[d + 1];
    for (int base = start; base < end; base += 32) {
        int idx = base + lane;
        bool ok = idx < end;
        int   sv = ok ? g_esrc[idx] : 0;
        float nv = ok ? g_enrm[idx] : 0.f;
        int cnt = end - base; if (cnt > 32) cnt = 32;
        int j = 0;
        for (; j + 1 < cnt; j += 2) {
            int   s0 = __shfl_sync(0xffffffffu, sv, j);
            int   s1 = __shfl_sync(0xffffffffu, sv, j + 1);
            float n0 = __shfl_sync(0xffffffffu, nv, j);
            float n1 = __shfl_sync(0xffffffffu, nv, j + 1);
            float4 v0 = H1[(size_t)s0 * 32 + lane];
            float4 v1 = H1[(size_t)s1 * 32 + lane];
            acc.x  = fmaf(v0.x, n0, acc.x);
            acc.y  = fmaf(v0.y, n0, acc.y);
            acc.z  = fmaf(v0.z, n0, acc.z);
            acc.w  = fmaf(v0.w, n0, acc.w);
            accB.x = fmaf(v1.x, n1, accB.x);
            accB.y = fmaf(v1.y, n1, accB.y);
            accB.z = fmaf(v1.z, n1, accB.z);
            accB.w = fmaf(v1.w, n1, accB.w);
        }
        if (j < cnt) {
            int   s0 = __shfl_sync(0xffffffffu, sv, j);
            float n0 = __shfl_sync(0xffffffffu, nv, j);
            float4 v0 = H1[(size_t)s0 * 32 + lane];
            acc.x = fmaf(v0.x, n0, acc.x);
            acc.y = fmaf(v0.y, n0, acc.y);
            acc.z = fmaf(v0.z, n0, acc.z);
            acc.w = fmaf(v0.w, n0, acc.w);
        }
    }
    acc.x += accB.x; acc.y += accB.y; acc.z += accB.z; acc.w += accB.w;

    float4 bv = ((const float4*)b1)[lane];
    acc.x = fmaxf(acc.x + bv.x, 0.f);
    acc.y = fmaxf(acc.y + bv.y, 0.f);
    acc.z = fmaxf(acc.z + bv.z, 0.f);
    acc.w = fmaxf(acc.w + bv.w, 0.f);

    size_t idx4 = (size_t)d * 32 + lane;
    ((float4*)g_hid)[idx4] = acc;
    ((float4*)out)[idx4] = acc;
}

// ---------------------------------------------------------------------------
// Gather layer 2: warp per dst node; lanes 0..19 hold one float2 (40 cols).
// Dual accumulators, precomputed nrm. Writes logits directly.
// ---------------------------------------------------------------------------
__global__ void k_gather2(const float* __restrict__ b2, float* __restrict__ out,
                          int n) {
    int w = (blockIdx.x * blockDim.x + threadIdx.x) >> 5;
    int lane = threadIdx.x & 31;
    if (w >= n) return;
    int d = w;
    bool act = lane < 20;
    float dd = g_dinv[d];
    const float2* H2 = (const float2*)g_H2;

    float2 acc = make_float2(0.f, 0.f);
    float2 accB = make_float2(0.f, 0.f);
    if (act) {
        acc = H2[(size_t)d * 20 + lane];
        float sl = dd * dd;
        acc.x *= sl; acc.y *= sl;
    }

    int start = g_off[d], end = g_off[d + 1];
    for (int base = start; base < end; base += 32) {
        int idx = base + lane;
        bool ok = idx < end;
        int   sv = ok ? g_esrc[idx] : 0;
        float nv = ok ? g_enrm[idx] : 0.f;
        int cnt = end - base; if (cnt > 32) cnt = 32;
        int j = 0;
        for (; j + 1 < cnt; j += 2) {
            int   s0 = __shfl_sync(0xffffffffu, sv, j);
            int   s1 = __shfl_sync(0xffffffffu, sv, j + 1);
            float n0 = __shfl_sync(0xffffffffu, nv, j);
            float n1 = __shfl_sync(0xffffffffu, nv, j + 1);
            if (act) {
                float2 v0 = H2[(size_t)s0 * 20 + lane];
                float2 v1 = H2[(size_t)s1 * 20 + lane];
                acc.x  = fmaf(v0.x, n0, acc.x);
                acc.y  = fmaf(v0.y, n0, acc.y);
                accB.x = fmaf(v1.x, n1, accB.x);
                accB.y = fmaf(v1.y, n1, accB.y);
            }
        }
        if (j < cnt) {
            int   s0 = __shfl_sync(0xffffffffu, sv, j);
            float n0 = __shfl_sync(0xffffffffu, nv, j);
            if (act) {
                float2 v0 = H2[(size_t)s0 * 20 + lane];
                acc.x = fmaf(v0.x, n0, acc.x);
                acc.y = fmaf(v0.y, n0, acc.y);
            }
        }
    }

    if (act) {
        acc.x += accB.x; acc.y += accB.y;
        float2 bv = ((const float2*)b2)[lane];
        acc.x += bv.x; acc.y += bv.y;
        ((float2*)out)[(size_t)d * 20 + lane] = acc;
    }
}

// ---------------------------------------------------------------------------
extern "C" void kernel_launch(void* const* d_in, const int* in_sizes, int n_in,
                              void* d_out, int out_size) {
    (void)n_in; (void)out_size;
    const float* x  = (const float*)d_in[0];
    const int*   ei = (const int*)d_in[1];     // int32 edge index
    const float* W1 = (const float*)d_in[2];
    const float* b1 = (const float*)d_in[3];
    const float* W2 = (const float*)d_in[4];
    const float* b2 = (const float*)d_in[5];

    int n = in_sizes[0] / 128;
    int E = in_sizes[1] / 2;
    const int* src = ei;
    const int* dst = ei + E;

    float* logits = (float*)d_out;                    // [n, 40]
    float* hidden = logits + (size_t)n * 40;          // [n, 128]

    const int B = 256;
    int nscan = (n + SCAN_B - 1) / SCAN_B;

    // Degree + norm
    k_deg_init<<<(n + B - 1) / B, B>>>(n);
    k_deg_count<<<(E + B - 1) / B, B>>>(dst, E, n);
    k_dinv<<<(n + B - 1) / B, B>>>(n);

    // CSR build (by dst), with precomputed edge norms
    k_scan1<<<nscan, SCAN_B>>>(n);
    k_scan2<<<1, MAXBLK>>>(nscan);
    k_scan3<<<(n + B - 1) / B, B>>>(n, E);
    k_bucket<<<(E + B - 1) / B, B>>>(src, dst, E, n);

    // Layer 1: GEMM then gather (fused bias+relu+output)
    k_gemm1<<<(n + 63) / 64, B>>>(x, W1, n);
    k_gather1<<<(n * 32 + B - 1) / B, B>>>(b1, hidden, n);

    // Layer 2: GEMM then gather (fused bias+output)
    k_gemm2<<<(n + 63) / 64, B>>>(W2, n);
    k_gather2<<<(n * 32 + B - 1) / B, B>>>(b2, logits, n);
}

// round 11
// speedup vs baseline: 2.7688x; 1.2027x over previous
#include <cuda_runtime.h>
#include <cstdint>

#define NMAX 100000
#define EMAX 1600000
#define SCAN_B 1024
#define MAXBLK 128   // >= ceil(NMAX/SCAN_B) = 98

// Scratch (allocation-free rule: __device__ globals).
__device__ float g_H1[(size_t)NMAX * 128];   // x @ W1
__device__ float g_H2[(size_t)NMAX * 40];    // hidden @ W2
__device__ float g_dinv[NMAX];
__device__ int   g_deg[NMAX];                // in-degree (no self loop)
__device__ int   g_off[NMAX + 1];            // CSR row offsets (by dst)
__device__ int   g_pos[NMAX];                // bucket cursors
__device__ int2  g_edge[EMAX];               // {src, bits(nrm)} per CSR slot
__device__ int   g_part[MAXBLK];             // scan partials
__device__ int   g_partx[MAXBLK];            // exclusive-scanned partials

__device__ __forceinline__ float to_tf32(float f) {
    uint32_t u;
    asm("cvt.rna.tf32.f32 %0, %1;" : "=r"(u) : "f"(f));
    return __uint_as_float(u);
}

// ---------------------------------------------------------------------------
// Degree count (g_deg zeroed by cudaMemsetAsync)
// ---------------------------------------------------------------------------
__global__ void k_deg_count(const int* __restrict__ dst, int E, int n) {
    int e = blockIdx.x * blockDim.x + threadIdx.x;
    if (e < E) {
        int d = dst[e];
        if ((unsigned)d < (unsigned)n) atomicAdd(&g_deg[d], 1);
    }
}

// ---------------------------------------------------------------------------
// CSR build: scan of edge counts; dinv fused into scan1.
// ---------------------------------------------------------------------------
__global__ void k_scan1(int n) {
    __shared__ int sh[SCAN_B];
    int tid = threadIdx.x;
    int i = blockIdx.x * SCAN_B + tid;
    int v = (i < n) ? g_deg[i] : 0;
    sh[tid] = v;
    __syncthreads();
    for (int off = 1; off < SCAN_B; off <<= 1) {
        int t = (tid >= off) ? sh[tid - off] : 0;
        __syncthreads();
        sh[tid] += t;
        __syncthreads();
    }
    if (i < n) {
        g_off[i] = sh[tid] - v;              // block-local exclusive
        g_dinv[i] = rsqrtf((float)(v + 1));  // +1 self loop
    }
    if (tid == SCAN_B - 1) g_part[blockIdx.x] = sh[tid];
}

__global__ void k_scan2(int nblocks) {
    __shared__ int sh[MAXBLK];
    int tid = threadIdx.x;
    int v = (tid < nblocks) ? g_part[tid] : 0;
    sh[tid] = v;
    __syncthreads();
    for (int off = 1; off < MAXBLK; off <<= 1) {
        int t = (tid >= off) ? sh[tid - off] : 0;
        __syncthreads();
        sh[tid] += t;
        __syncthreads();
    }
    if (tid < nblocks) g_partx[tid] = sh[tid] - v;  // exclusive
}

__global__ void k_scan3(int n, int E) {
    int i = blockIdx.x * blockDim.x + threadIdx.x;
    if (i < n) {
        int o = g_off[i] + g_partx[i / SCAN_B];
        g_off[i] = o;
        g_pos[i] = o;
    }
    if (i == 0) g_off[n] = E;
}

__global__ void k_bucket(const int* __restrict__ src,
                         const int* __restrict__ dst, int E, int n) {
    int e = blockIdx.x * blockDim.x + threadIdx.x;
    if (e >= E) return;
    int s = src[e], d = dst[e];
    if ((unsigned)s >= (unsigned)n || (unsigned)d >= (unsigned)n) return;
    float nrm = g_dinv[s] * g_dinv[d];
    int p = atomicAdd(&g_pos[d], 1);
    g_edge[p] = make_int2(s, __float_as_int(nrm));
}

// ---------------------------------------------------------------------------
// GEMM1 (tf32 tensor cores): g_H1[n,128] = X[n,128] @ W1[128,128]
// Block tile 128x128, 8 warps, each warp a 16-row strip (16x128).
// mma.sync.m16n8k8 tf32, fp32 accumulate. Operands pre-rounded to tf32
// at smem-fill time.
// ---------------------------------------------------------------------------
__global__ void k_gemm1(const float* __restrict__ X, const float* __restrict__ W,
                        int n) {
    __shared__ float Xs[128][36];   // [row][kk], pad 36 -> conflict-free frags
    __shared__ float Ws[32][132];   // [kk][n], pad 132
    int tid = threadIdx.x;
    int warp = tid >> 5, lane = tid & 31;
    int rowBase = blockIdx.x * 128;
    int r0 = warp * 16;

    float c[16][4];
#pragma unroll
    for (int t = 0; t < 16; t++)
#pragma unroll
        for (int q = 0; q < 4; q++) c[t][q] = 0.f;

    for (int k0 = 0; k0 < 128; k0 += 32) {
        // X tile: 128 rows x 32 k (tf32-rounded), float4 loads
        for (int i = tid; i < 1024; i += 256) {
            int row = i >> 3, c4 = (i & 7) * 4;
            int grow = rowBase + row;
            float4 v = make_float4(0.f, 0.f, 0.f, 0.f);
            if (grow < n) v = *(const float4*)&X[(size_t)grow * 128 + k0 + c4];
            Xs[row][c4 + 0] = to_tf32(v.x);
            Xs[row][c4 + 1] = to_tf32(v.y);
            Xs[row][c4 + 2] = to_tf32(v.z);
            Xs[row][c4 + 3] = to_tf32(v.w);
        }
        // W panel: 32 k x 128 n (tf32-rounded), float4 loads, contiguous STS
        for (int i = tid; i < 1024; i += 256) {
            int k = i >> 5, n4 = (i & 31) * 4;
            float4 v = *(const float4*)&W[(size_t)(k0 + k) * 128 + n4];
            Ws[k][n4 + 0] = to_tf32(v.x);
            Ws[k][n4 + 1] = to_tf32(v.y);
            Ws[k][n4 + 2] = to_tf32(v.z);
            Ws[k][n4 + 3] = to_tf32(v.w);
        }
        __syncthreads();

        int qr = lane >> 2, qc = lane & 3;
#pragma unroll
        for (int ks = 0; ks < 32; ks += 8) {
            uint32_t a0 = __float_as_uint(Xs[r0 + qr][ks + qc]);
            uint32_t a1 = __float_as_uint(Xs[r0 + qr + 8][ks + qc]);
            uint32_t a2 = __float_as_uint(Xs[r0 + qr][ks + qc + 4]);
            uint32_t a3 = __float_as_uint(Xs[r0 + qr + 8][ks + qc + 4]);
#pragma unroll
            for (int nt = 0; nt < 16; nt++) {
                uint32_t b0 = __float_as_uint(Ws[ks + qc][nt * 8 + qr]);
                uint32_t b1 = __float_as_uint(Ws[ks + qc + 4][nt * 8 + qr]);
                asm volatile(
                    "mma.sync.aligned.m16n8k8.row.col.f32.tf32.tf32.f32 "
                    "{%0,%1,%2,%3}, {%4,%5,%6,%7}, {%8,%9}, {%0,%1,%2,%3};"
                    : "+f"(c[nt][0]), "+f"(c[nt][1]), "+f"(c[nt][2]), "+f"(c[nt][3])
                    : "r"(a0), "r"(a1), "r"(a2), "r"(a3), "r"(b0), "r"(b1));
            }
        }
        __syncthreads();
    }

    int qr = lane >> 2, qc = lane & 3;
    int row0 = rowBase + r0 + qr;
    int row1 = row0 + 8;
#pragma unroll
    for (int nt = 0; nt < 16; nt++) {
        int col = nt * 8 + qc * 2;
        if (row0 < n) *(float2*)&g_H1[(size_t)row0 * 128 + col] = make_float2(c[nt][0], c[nt][1]);
        if (row1 < n) *(float2*)&g_H1[(size_t)row1 * 128 + col] = make_float2(c[nt][2], c[nt][3]);
    }
}

// ---------------------------------------------------------------------------
// GEMM2: g_H2[n,40] = hidden[n,128] @ W2[128,40] (fp32, hidden from d_out)
// ---------------------------------------------------------------------------
__global__ void k_gemm2(const float* __restrict__ Hin, const float* __restrict__ W2,
                        int n) {
    __shared__ float Ws[128 * 48];
    __shared__ float Xs[64 * 32];
    int tid = threadIdx.x;
    int warp = tid >> 5, lane = tid & 31;
    int rowBase = blockIdx.x * 64;
    int r0 = warp * 8;

    for (int i = tid; i < 128 * 48; i += 256) {
        int k = i / 48, c = i - k * 48;
        Ws[i] = (c < 40) ? W2[k * 40 + c] : 0.f;
    }

    float2 acc[8];
#pragma unroll
    for (int r = 0; r < 8; r++) acc[r] = make_float2(0.f, 0.f);

    for (int k0 = 0; k0 < 128; k0 += 32) {
        for (int i = tid; i < 64 * 32; i += 256) {
            int row = i >> 5, kk = i & 31;
            int grow = rowBase + row;
            Xs[i] = (grow < n) ? Hin[(size_t)grow * 128 + k0 + kk] : 0.f;
        }
        __syncthreads();

        const float2* Wsf2 = (const float2*)Ws;
        int wcol = (lane < 24) ? lane : 0;
#pragma unroll
        for (int kk = 0; kk < 32; kk += 4) {
            float2 w0 = Wsf2[(k0 + kk + 0) * 24 + wcol];
            float2 w1 = Wsf2[(k0 + kk + 1) * 24 + wcol];
            float2 w2 = Wsf2[(k0 + kk + 2) * 24 + wcol];
            float2 w3 = Wsf2[(k0 + kk + 3) * 24 + wcol];
#pragma unroll
            for (int r = 0; r < 8; r++) {
                float4 xv = *(const float4*)&Xs[(r0 + r) * 32 + kk];
                acc[r].x = fmaf(xv.x, w0.x, acc[r].x);
                acc[r].y = fmaf(xv.x, w0.y, acc[r].y);
                acc[r].x = fmaf(xv.y, w1.x, acc[r].x);
                acc[r].y = fmaf(xv.y, w1.y, acc[r].y);
                acc[r].x = fmaf(xv.z, w2.x, acc[r].x);
                acc[r].y = fmaf(xv.z, w2.y, acc[r].y);
                acc[r].x = fmaf(xv.w, w3.x, acc[r].x);
                acc[r].y = fmaf(xv.w, w3.y, acc[r].y);
            }
        }
        __syncthreads();
    }

    int c = lane * 2;
    if (c < 40) {
#pragma unroll
        for (int r = 0; r < 8; r++) {
            int row = rowBase + r0 + r;
            if (row < n) *(float2*)(g_H2 + (size_t)row * 40 + c) = acc[r];
        }
    }
}

// ---------------------------------------------------------------------------
// Gather layer 1: warp per dst node, dual accumulators, packed edge records.
// Writes hidden ONLY to d_out (gemm2 reads it from there).
// ---------------------------------------------------------------------------
__global__ void k_gather1(const float* __restrict__ b1, float* __restrict__ out,
                          int n) {
    int w = (blockIdx.x * blockDim.x + threadIdx.x) >> 5;
    int lane = threadIdx.x & 31;
    if (w >= n) return;
    int d = w;
    float dd = g_dinv[d];
    const float4* H1 = (const float4*)g_H1;

    float4 acc = H1[(size_t)d * 32 + lane];
    float sl = dd * dd;
    acc.x *= sl; acc.y *= sl; acc.z *= sl; acc.w *= sl;
    float4 accB = make_float4(0.f, 0.f, 0.f, 0.f);

    int start = g_off[d], end = g_off[d + 1];
    for (int base = start; base < end; base += 32) {
        int idx = base + lane;
        int2 ev = (idx < end) ? g_edge[idx] : make_int2(0, 0);
        int   sv = ev.x;
        float nv = __int_as_float(ev.y);
        int cnt = end - base; if (cnt > 32) cnt = 32;
        int j = 0;
        for (; j + 1 < cnt; j += 2) {
            int   s0 = __shfl_sync(0xffffffffu, sv, j);
            int   s1 = __shfl_sync(0xffffffffu, sv, j + 1);
            float n0 = __shfl_sync(0xffffffffu, nv, j);
            float n1 = __shfl_sync(0xffffffffu, nv, j + 1);
            float4 v0 = H1[(size_t)s0 * 32 + lane];
            float4 v1 = H1[(size_t)s1 * 32 + lane];
            acc.x  = fmaf(v0.x, n0, acc.x);
            acc.y  = fmaf(v0.y, n0, acc.y);
            acc.z  = fmaf(v0.z, n0, acc.z);
            acc.w  = fmaf(v0.w, n0, acc.w);
            accB.x = fmaf(v1.x, n1, accB.x);
            accB.y = fmaf(v1.y, n1, accB.y);
            accB.z = fmaf(v1.z, n1, accB.z);
            accB.w = fmaf(v1.w, n1, accB.w);
        }
        if (j < cnt) {
            int   s0 = __shfl_sync(0xffffffffu, sv, j);
            float n0 = __shfl_sync(0xffffffffu, nv, j);
            float4 v0 = H1[(size_t)s0 * 32 + lane];
            acc.x = fmaf(v0.x, n0, acc.x);
            acc.y = fmaf(v0.y, n0, acc.y);
            acc.z = fmaf(v0.z, n0, acc.z);
            acc.w = fmaf(v0.w, n0, acc.w);
        }
    }
    acc.x += accB.x; acc.y += accB.y; acc.z += accB.z; acc.w += accB.w;

    float4 bv = ((const float4*)b1)[lane];
    acc.x = fmaxf(acc.x + bv.x, 0.f);
    acc.y = fmaxf(acc.y + bv.y, 0.f);
    acc.z = fmaxf(acc.z + bv.z, 0.f);
    acc.w = fmaxf(acc.w + bv.w, 0.f);

    ((float4*)out)[(size_t)d * 32 + lane] = acc;
}

// ---------------------------------------------------------------------------
// Gather layer 2: warp per dst; lanes 0..19 hold one float2 (40 cols).
// ---------------------------------------------------------------------------
__global__ void k_gather2(const float* __restrict__ b2, float* __restrict__ out,
                          int n) {
    int w = (blockIdx.x * blockDim.x + threadIdx.x) >> 5;
    int lane = threadIdx.x & 31;
    if (w >= n) return;
    int d = w;
    bool act = lane < 20;
    float dd = g_dinv[d];
    const float2* H2 = (const float2*)g_H2;

    float2 acc = make_float2(0.f, 0.f);
    float2 accB = make_float2(0.f, 0.f);
    if (act) {
        acc = H2[(size_t)d * 20 + lane];
        float sl = dd * dd;
        acc.x *= sl; acc.y *= sl;
    }

    int start = g_off[d], end = g_off[d + 1];
    for (int base = start; base < end; base += 32) {
        int idx = base + lane;
        int2 ev = (idx < end) ? g_edge[idx] : make_int2(0, 0);
        int   sv = ev.x;
        float nv = __int_as_float(ev.y);
        int cnt = end - base; if (cnt > 32) cnt = 32;
        int j = 0;
        for (; j + 1 < cnt; j += 2) {
            int   s0 = __shfl_sync(0xffffffffu, sv, j);
            int   s1 = __shfl_sync(0xffffffffu, sv, j + 1);
            float n0 = __shfl_sync(0xffffffffu, nv, j);
            float n1 = __shfl_sync(0xffffffffu, nv, j + 1);
            if (act) {
                float2 v0 = H2[(size_t)s0 * 20 + lane];
                float2 v1 = H2[(size_t)s1 * 20 + lane];
                acc.x  = fmaf(v0.x, n0, acc.x);
                acc.y  = fmaf(v0.y, n0, acc.y);
                accB.x = fmaf(v1.x, n1, accB.x);
                accB.y = fmaf(v1.y, n1, accB.y);
            }
        }
        if (j < cnt) {
            int   s0 = __shfl_sync(0xffffffffu, sv, j);
            float n0 = __shfl_sync(0xffffffffu, nv, j);
            if (act) {
                float2 v0 = H2[(size_t)s0 * 20 + lane];
                acc.x = fmaf(v0.x, n0, acc.x);
                acc.y = fmaf(v0.y, n0, acc.y);
            }
        }
    }

    if (act) {
        acc.x += accB.x; acc.y += accB.y;
        float2 bv = ((const float2*)b2)[lane];
        acc.x += bv.x; acc.y += bv.y;
        ((float2*)out)[(size_t)d * 20 + lane] = acc;
    }
}

// ---------------------------------------------------------------------------
extern "C" void kernel_launch(void* const* d_in, const int* in_sizes, int n_in,
                              void* d_out, int out_size) {
    (void)n_in; (void)out_size;
    const float* x  = (const float*)d_in[0];
    const int*   ei = (const int*)d_in[1];     // int32 edge index
    const float* W1 = (const float*)d_in[2];
    const float* b1 = (const float*)d_in[3];
    const float* W2 = (const float*)d_in[4];
    const float* b2 = (const float*)d_in[5];

    int n = in_sizes[0] / 128;
    int E = in_sizes[1] / 2;
    const int* src = ei;
    const int* dst = ei + E;

    float* logits = (float*)d_out;                    // [n, 40]
    float* hidden = logits + (size_t)n * 40;          // [n, 128]

    const int B = 256;
    int nscan = (n + SCAN_B - 1) / SCAN_B;

    // Degree (zero via memset node) + CSR build with fused dinv
    void* degPtr = nullptr;
    cudaGetSymbolAddress(&degPtr, g_deg);
    cudaMemsetAsync(degPtr, 0, (size_t)n * sizeof(int));

    k_deg_count<<<(E + B - 1) / B, B>>>(dst, E, n);
    k_scan1<<<nscan, SCAN_B>>>(n);
    k_scan2<<<1, MAXBLK>>>(nscan);
    k_scan3<<<(n + B - 1) / B, B>>>(n, E);
    k_bucket<<<(E + B - 1) / B, B>>>(src, dst, E, n);

    // Layer 1: tf32 tensor GEMM then gather (fused bias+relu -> d_out hidden)
    k_gemm1<<<(n + 127) / 128, B>>>(x, W1, n);
    k_gather1<<<(n * 32 + B - 1) / B, B>>>(b1, hidden, n);

    // Layer 2: GEMM (reads hidden from d_out) then gather -> logits
    k_gemm2<<<(n + 63) / 64, B>>>(hidden, W2, n);
    k_gather2<<<(n * 32 + B - 1) / B, B>>>(b2, logits, n);
}

// round 12
// speedup vs baseline: 3.1671x; 1.1438x over previous
#include <cuda_runtime.h>
#include <cstdint>

#define NMAX 100000
#define EMAX 1600000
#define SCAN_B 1024
#define MAXBLK 128   // >= ceil(NMAX/SCAN_B) = 98

// Scratch (allocation-free rule: __device__ globals).
__device__ float g_H1[(size_t)NMAX * 128];   // x @ W1
__device__ float g_H2[(size_t)NMAX * 40];    // hidden @ W2
__device__ float g_dinv[NMAX];
__device__ int   g_deg[NMAX];                // in-degree (no self loop)
__device__ int   g_off[NMAX + 1];            // CSR row offsets (by dst)
__device__ int   g_pos[NMAX];                // bucket cursors
__device__ int2  g_edge[EMAX];               // {src, bits(nrm)} per CSR slot
__device__ int   g_part[MAXBLK];             // scan partials
__device__ int   g_partx[MAXBLK];            // exclusive-scanned partials

__device__ __forceinline__ float to_tf32(float f) {
    uint32_t u;
    asm("cvt.rna.tf32.f32 %0, %1;" : "=r"(u) : "f"(f));
    return __uint_as_float(u);
}

// ---------------------------------------------------------------------------
// Degree count, 4 edges per thread (g_deg zeroed by cudaMemsetAsync)
// ---------------------------------------------------------------------------
__global__ void k_deg_count(const int* __restrict__ dst, int E, int n) {
    int t = blockIdx.x * blockDim.x + threadIdx.x;
    int e0 = t * 4;
    if (e0 + 3 < E) {
        int4 d4 = *(const int4*)(dst + e0);
        if ((unsigned)d4.x < (unsigned)n) atomicAdd(&g_deg[d4.x], 1);
        if ((unsigned)d4.y < (unsigned)n) atomicAdd(&g_deg[d4.y], 1);
        if ((unsigned)d4.z < (unsigned)n) atomicAdd(&g_deg[d4.z], 1);
        if ((unsigned)d4.w < (unsigned)n) atomicAdd(&g_deg[d4.w], 1);
    } else {
        for (int e = e0; e < E; e++) {
            int d = dst[e];
            if ((unsigned)d < (unsigned)n) atomicAdd(&g_deg[d], 1);
        }
    }
}

// ---------------------------------------------------------------------------
// CSR build: scan of edge counts; dinv fused into scan1.
// ---------------------------------------------------------------------------
__global__ void k_scan1(int n) {
    __shared__ int sh[SCAN_B];
    int tid = threadIdx.x;
    int i = blockIdx.x * SCAN_B + tid;
    int v = (i < n) ? g_deg[i] : 0;
    sh[tid] = v;
    __syncthreads();
    for (int off = 1; off < SCAN_B; off <<= 1) {
        int t = (tid >= off) ? sh[tid - off] : 0;
        __syncthreads();
        sh[tid] += t;
        __syncthreads();
    }
    if (i < n) {
        g_off[i] = sh[tid] - v;              // block-local exclusive
        g_dinv[i] = rsqrtf((float)(v + 1));  // +1 self loop
    }
    if (tid == SCAN_B - 1) g_part[blockIdx.x] = sh[tid];
}

__global__ void k_scan2(int nblocks) {
    __shared__ int sh[MAXBLK];
    int tid = threadIdx.x;
    int v = (tid < nblocks) ? g_part[tid] : 0;
    sh[tid] = v;
    __syncthreads();
    for (int off = 1; off < MAXBLK; off <<= 1) {
        int t = (tid >= off) ? sh[tid - off] : 0;
        __syncthreads();
        sh[tid] += t;
        __syncthreads();
    }
    if (tid < nblocks) g_partx[tid] = sh[tid] - v;  // exclusive
}

__global__ void k_scan3(int n, int E) {
    int i = blockIdx.x * blockDim.x + threadIdx.x;
    if (i < n) {
        int o = g_off[i] + g_partx[i / SCAN_B];
        g_off[i] = o;
        g_pos[i] = o;
    }
    if (i == 0) g_off[n] = E;
}

__global__ void k_bucket(const int* __restrict__ src,
                         const int* __restrict__ dst, int E, int n) {
    int e = blockIdx.x * blockDim.x + threadIdx.x;
    if (e >= E) return;
    int s = src[e], d = dst[e];
    if ((unsigned)s >= (unsigned)n || (unsigned)d >= (unsigned)n) return;
    float nrm = g_dinv[s] * g_dinv[d];
    int p = atomicAdd(&g_pos[d], 1);
    g_edge[p] = make_int2(s, __float_as_int(nrm));
}

// ---------------------------------------------------------------------------
// GEMM1 (tf32 tensor cores): g_H1[n,128] = X[n,128] @ W1[128,128]
// Block tile 128x128, 8 warps, each warp a 16-row strip (16x128).
// ---------------------------------------------------------------------------
__global__ void k_gemm1(const float* __restrict__ X, const float* __restrict__ W,
                        int n) {
    __shared__ float Xs[128][36];   // [row][kk]
    __shared__ float Ws[32][132];   // [kk][n]
    int tid = threadIdx.x;
    int warp = tid >> 5, lane = tid & 31;
    int rowBase = blockIdx.x * 128;
    int r0 = warp * 16;

    float c[16][4];
#pragma unroll
    for (int t = 0; t < 16; t++)
#pragma unroll
        for (int q = 0; q < 4; q++) c[t][q] = 0.f;

    for (int k0 = 0; k0 < 128; k0 += 32) {
        for (int i = tid; i < 1024; i += 256) {
            int row = i >> 3, c4 = (i & 7) * 4;
            int grow = rowBase + row;
            float4 v = make_float4(0.f, 0.f, 0.f, 0.f);
            if (grow < n) v = *(const float4*)&X[(size_t)grow * 128 + k0 + c4];
            Xs[row][c4 + 0] = to_tf32(v.x);
            Xs[row][c4 + 1] = to_tf32(v.y);
            Xs[row][c4 + 2] = to_tf32(v.z);
            Xs[row][c4 + 3] = to_tf32(v.w);
        }
        for (int i = tid; i < 1024; i += 256) {
            int k = i >> 5, n4 = (i & 31) * 4;
            float4 v = *(const float4*)&W[(size_t)(k0 + k) * 128 + n4];
            Ws[k][n4 + 0] = to_tf32(v.x);
            Ws[k][n4 + 1] = to_tf32(v.y);
            Ws[k][n4 + 2] = to_tf32(v.z);
            Ws[k][n4 + 3] = to_tf32(v.w);
        }
        __syncthreads();

        int qr = lane >> 2, qc = lane & 3;
#pragma unroll
        for (int ks = 0; ks < 32; ks += 8) {
            uint32_t a0 = __float_as_uint(Xs[r0 + qr][ks + qc]);
            uint32_t a1 = __float_as_uint(Xs[r0 + qr + 8][ks + qc]);
            uint32_t a2 = __float_as_uint(Xs[r0 + qr][ks + qc + 4]);
            uint32_t a3 = __float_as_uint(Xs[r0 + qr + 8][ks + qc + 4]);
#pragma unroll
            for (int nt = 0; nt < 16; nt++) {
                uint32_t b0 = __float_as_uint(Ws[ks + qc][nt * 8 + qr]);
                uint32_t b1 = __float_as_uint(Ws[ks + qc + 4][nt * 8 + qr]);
                asm volatile(
                    "mma.sync.aligned.m16n8k8.row.col.f32.tf32.tf32.f32 "
                    "{%0,%1,%2,%3}, {%4,%5,%6,%7}, {%8,%9}, {%0,%1,%2,%3};"
                    : "+f"(c[nt][0]), "+f"(c[nt][1]), "+f"(c[nt][2]), "+f"(c[nt][3])
                    : "r"(a0), "r"(a1), "r"(a2), "r"(a3), "r"(b0), "r"(b1));
            }
        }
        __syncthreads();
    }

    int qr = lane >> 2, qc = lane & 3;
    int row0 = rowBase + r0 + qr;
    int row1 = row0 + 8;
#pragma unroll
    for (int nt = 0; nt < 16; nt++) {
        int col = nt * 8 + qc * 2;
        if (row0 < n) *(float2*)&g_H1[(size_t)row0 * 128 + col] = make_float2(c[nt][0], c[nt][1]);
        if (row1 < n) *(float2*)&g_H1[(size_t)row1 * 128 + col] = make_float2(c[nt][2], c[nt][3]);
    }
}

// ---------------------------------------------------------------------------
// GEMM2 (tf32 tensor cores): g_H2[n,40] = hidden[n,128] @ W2[128,40]
// Block tile 128 rows, 8 warps x 16-row strip, 5 n-tiles of 8 cols.
// ---------------------------------------------------------------------------
__global__ void k_gemm2(const float* __restrict__ Hin, const float* __restrict__ W2,
                        int n) {
    __shared__ float Xs[128][36];   // [row][kk]
    __shared__ float Ws[32][44];    // [kk][col<40]
    int tid = threadIdx.x;
    int warp = tid >> 5, lane = tid & 31;
    int rowBase = blockIdx.x * 128;
    int r0 = warp * 16;

    float c[5][4];
#pragma unroll
    for (int t = 0; t < 5; t++)
#pragma unroll
        for (int q = 0; q < 4; q++) c[t][q] = 0.f;

    for (int k0 = 0; k0 < 128; k0 += 32) {
        for (int i = tid; i < 1024; i += 256) {
            int row = i >> 3, c4 = (i & 7) * 4;
            int grow = rowBase + row;
            float4 v = make_float4(0.f, 0.f, 0.f, 0.f);
            if (grow < n) v = *(const float4*)&Hin[(size_t)grow * 128 + k0 + c4];
            Xs[row][c4 + 0] = to_tf32(v.x);
            Xs[row][c4 + 1] = to_tf32(v.y);
            Xs[row][c4 + 2] = to_tf32(v.z);
            Xs[row][c4 + 3] = to_tf32(v.w);
        }
        // W2 panel: 32 k x 40 cols = 320 float4
        for (int i = tid; i < 320; i += 256) {
            int k = i / 10, c4 = (i - k * 10) * 4;
            float4 v = *(const float4*)&W2[(size_t)(k0 + k) * 40 + c4];
            Ws[k][c4 + 0] = to_tf32(v.x);
            Ws[k][c4 + 1] = to_tf32(v.y);
            Ws[k][c4 + 2] = to_tf32(v.z);
            Ws[k][c4 + 3] = to_tf32(v.w);
        }
        __syncthreads();

        int qr = lane >> 2, qc = lane & 3;
#pragma unroll
        for (int ks = 0; ks < 32; ks += 8) {
            uint32_t a0 = __float_as_uint(Xs[r0 + qr][ks + qc]);
            uint32_t a1 = __float_as_uint(Xs[r0 + qr + 8][ks + qc]);
            uint32_t a2 = __float_as_uint(Xs[r0 + qr][ks + qc + 4]);
            uint32_t a3 = __float_as_uint(Xs[r0 + qr + 8][ks + qc + 4]);
#pragma unroll
            for (int nt = 0; nt < 5; nt++) {
                uint32_t b0 = __float_as_uint(Ws[ks + qc][nt * 8 + qr]);
                uint32_t b1 = __float_as_uint(Ws[ks + qc + 4][nt * 8 + qr]);
                asm volatile(
                    "mma.sync.aligned.m16n8k8.row.col.f32.tf32.tf32.f32 "
                    "{%0,%1,%2,%3}, {%4,%5,%6,%7}, {%8,%9}, {%0,%1,%2,%3};"
                    : "+f"(c[nt][0]), "+f"(c[nt][1]), "+f"(c[nt][2]), "+f"(c[nt][3])
                    : "r"(a0), "r"(a1), "r"(a2), "r"(a3), "r"(b0), "r"(b1));
            }
        }
        __syncthreads();
    }

    int qr = lane >> 2, qc = lane & 3;
    int row0 = rowBase + r0 + qr;
    int row1 = row0 + 8;
#pragma unroll
    for (int nt = 0; nt < 5; nt++) {
        int col = nt * 8 + qc * 2;
        if (row0 < n) *(float2*)&g_H2[(size_t)row0 * 40 + col] = make_float2(c[nt][0], c[nt][1]);
        if (row1 < n) *(float2*)&g_H2[(size_t)row1 * 40 + col] = make_float2(c[nt][2], c[nt][3]);
    }
}

// ---------------------------------------------------------------------------
// Gather layer 1: warp per dst node, dual accumulators, packed edge records.
// ---------------------------------------------------------------------------
__global__ void k_gather1(const float* __restrict__ b1, float* __restrict__ out,
                          int n) {
    int w = (blockIdx.x * blockDim.x + threadIdx.x) >> 5;
    int lane = threadIdx.x & 31;
    if (w >= n) return;
    int d = w;
    float dd = g_dinv[d];
    const float4* H1 = (const float4*)g_H1;

    float4 acc = H1[(size_t)d * 32 + lane];
    float sl = dd * dd;
    acc.x *= sl; acc.y *= sl; acc.z *= sl; acc.w *= sl;
    float4 accB = make_float4(0.f, 0.f, 0.f, 0.f);

    int start = g_off[d], end = g_off[d + 1];
    for (int base = start; base < end; base += 32) {
        int idx = base + lane;
        int2 ev = (idx < end) ? g_edge[idx] : make_int2(0, 0);
        int   sv = ev.x;
        float nv = __int_as_float(ev.y);
        int cnt = end - base; if (cnt > 32) cnt = 32;
        int j = 0;
        for (; j + 1 < cnt; j += 2) {
            int   s0 = __shfl_sync(0xffffffffu, sv, j);
            int   s1 = __shfl_sync(0xffffffffu, sv, j + 1);
            float n0 = __shfl_sync(0xffffffffu, nv, j);
            float n1 = __shfl_sync(0xffffffffu, nv, j + 1);
            float4 v0 = H1[(size_t)s0 * 32 + lane];
            float4 v1 = H1[(size_t)s1 * 32 + lane];
            acc.x  = fmaf(v0.x, n0, acc.x);
            acc.y  = fmaf(v0.y, n0, acc.y);
            acc.z  = fmaf(v0.z, n0, acc.z);
            acc.w  = fmaf(v0.w, n0, acc.w);
            accB.x = fmaf(v1.x, n1, accB.x);
            accB.y = fmaf(v1.y, n1, accB.y);
            accB.z = fmaf(v1.z, n1, accB.z);
            accB.w = fmaf(v1.w, n1, accB.w);
        }
        if (j < cnt) {
            int   s0 = __shfl_sync(0xffffffffu, sv, j);
            float n0 = __shfl_sync(0xffffffffu, nv, j);
            float4 v0 = H1[(size_t)s0 * 32 + lane];
            acc.x = fmaf(v0.x, n0, acc.x);
            acc.y = fmaf(v0.y, n0, acc.y);
            acc.z = fmaf(v0.z, n0, acc.z);
            acc.w = fmaf(v0.w, n0, acc.w);
        }
    }
    acc.x += accB.x; acc.y += accB.y; acc.z += accB.z; acc.w += accB.w;

    float4 bv = ((const float4*)b1)[lane];
    acc.x = fmaxf(acc.x + bv.x, 0.f);
    acc.y = fmaxf(acc.y + bv.y, 0.f);
    acc.z = fmaxf(acc.z + bv.z, 0.f);
    acc.w = fmaxf(acc.w + bv.w, 0.f);

    ((float4*)out)[(size_t)d * 32 + lane] = acc;
}

// ---------------------------------------------------------------------------
// Gather layer 2: warp per dst; lanes 0..19 hold one float2 (40 cols).
// ---------------------------------------------------------------------------
__global__ void k_gather2(const float* __restrict__ b2, float* __restrict__ out,
                          int n) {
    int w = (blockIdx.x * blockDim.x + threadIdx.x) >> 5;
    int lane = threadIdx.x & 31;
    if (w >= n) return;
    int d = w;
    bool act = lane < 20;
    float dd = g_dinv[d];
    const float2* H2 = (const float2*)g_H2;

    float2 acc = make_float2(0.f, 0.f);
    float2 accB = make_float2(0.f, 0.f);
    if (act) {
        acc = H2[(size_t)d * 20 + lane];
        float sl = dd * dd;
        acc.x *= sl; acc.y *= sl;
    }

    int start = g_off[d], end = g_off[d + 1];
    for (int base = start; base < end; base += 32) {
        int idx = base + lane;
        int2 ev = (idx < end) ? g_edge[idx] : make_int2(0, 0);
        int   sv = ev.x;
        float nv = __int_as_float(ev.y);
        int cnt = end - base; if (cnt > 32) cnt = 32;
        int j = 0;
        for (; j + 1 < cnt; j += 2) {
            int   s0 = __shfl_sync(0xffffffffu, sv, j);
            int   s1 = __shfl_sync(0xffffffffu, sv, j + 1);
            float n0 = __shfl_sync(0xffffffffu, nv, j);
            float n1 = __shfl_sync(0xffffffffu, nv, j + 1);
            if (act) {
                float2 v0 = H2[(size_t)s0 * 20 + lane];
                float2 v1 = H2[(size_t)s1 * 20 + lane];
                acc.x  = fmaf(v0.x, n0, acc.x);
                acc.y  = fmaf(v0.y, n0, acc.y);
                accB.x = fmaf(v1.x, n1, accB.x);
                accB.y = fmaf(v1.y, n1, accB.y);
            }
        }
        if (j < cnt) {
            int   s0 = __shfl_sync(0xffffffffu, sv, j);
            float n0 = __shfl_sync(0xffffffffu, nv, j);
            if (act) {
                float2 v0 = H2[(size_t)s0 * 20 + lane];
                acc.x = fmaf(v0.x, n0, acc.x);
                acc.y = fmaf(v0.y, n0, acc.y);
            }
        }
    }

    if (act) {
        acc.x += accB.x; acc.y += accB.y;
        float2 bv = ((const float2*)b2)[lane];
        acc.x += bv.x; acc.y += bv.y;
        ((float2*)out)[(size_t)d * 20 + lane] = acc;
    }
}

// ---------------------------------------------------------------------------
extern "C" void kernel_launch(void* const* d_in, const int* in_sizes, int n_in,
                              void* d_out, int out_size) {
    (void)n_in; (void)out_size;
    const float* x  = (const float*)d_in[0];
    const int*   ei = (const int*)d_in[1];     // int32 edge index
    const float* W1 = (const float*)d_in[2];
    const float* b1 = (const float*)d_in[3];
    const float* W2 = (const float*)d_in[4];
    const float* b2 = (const float*)d_in[5];

    int n = in_sizes[0] / 128;
    int E = in_sizes[1] / 2;
    const int* src = ei;
    const int* dst = ei + E;

    float* logits = (float*)d_out;                    // [n, 40]
    float* hidden = logits + (size_t)n * 40;          // [n, 128]

    const int B = 256;
    int nscan = (n + SCAN_B - 1) / SCAN_B;

    void* degPtr = nullptr;
    cudaGetSymbolAddress(&degPtr, g_deg);
    cudaMemsetAsync(degPtr, 0, (size_t)n * sizeof(int));

    k_deg_count<<<((E + 3) / 4 + B - 1) / B, B>>>(dst, E, n);
    k_scan1<<<nscan, SCAN_B>>>(n);
    k_scan2<<<1, MAXBLK>>>(nscan);
    k_scan3<<<(n + B - 1) / B, B>>>(n, E);
    k_bucket<<<(E + B - 1) / B, B>>>(src, dst, E, n);

    // Layer 1: tf32 tensor GEMM then gather (fused bias+relu -> d_out hidden)
    k_gemm1<<<(n + 127) / 128, B>>>(x, W1, n);
    k_gather1<<<(n * 32 + B - 1) / B, B>>>(b1, hidden, n);

    // Layer 2: tf32 tensor GEMM (reads hidden from d_out) then gather
    k_gemm2<<<(n + 127) / 128, B>>>(hidden, W2, n);
    k_gather2<<<(n * 32 + B - 1) / B, B>>>(b2, logits, n);
}

// round 13
// speedup vs baseline: 3.2726x; 1.0333x over previous
#include <cuda_runtime.h>
#include <cuda_fp16.h>
#include <cstdint>

#define NMAX 100000
#define EMAX 1600000
#define SCAN_B 1024
#define MAXBLK 128   // >= ceil(NMAX/SCAN_B) = 98

// Scratch (allocation-free rule: __device__ globals).
__device__ __half g_H1[(size_t)NMAX * 128];  // x @ W1 (fp16 storage)
__device__ __half g_H2[(size_t)NMAX * 40];   // hidden @ W2 (fp16 storage)
__device__ float g_dinv[NMAX];
__device__ int   g_deg[NMAX];                // in-degree (no self loop)
__device__ int   g_off[NMAX + 1];            // CSR row offsets (by dst)
__device__ int   g_pos[NMAX];                // bucket cursors
__device__ int2  g_edge[EMAX];               // {src, bits(nrm)} per CSR slot
__device__ int   g_part[MAXBLK];             // scan partials
__device__ int   g_partx[MAXBLK];            // exclusive-scanned partials

__device__ __forceinline__ float to_tf32(float f) {
    uint32_t u;
    asm("cvt.rna.tf32.f32 %0, %1;" : "=r"(u) : "f"(f));
    return __uint_as_float(u);
}

// ---------------------------------------------------------------------------
// Degree count, 4 edges per thread (g_deg zeroed by cudaMemsetAsync)
// ---------------------------------------------------------------------------
__global__ void k_deg_count(const int* __restrict__ dst, int E, int n) {
    int t = blockIdx.x * blockDim.x + threadIdx.x;
    int e0 = t * 4;
    if (e0 + 3 < E) {
        int4 d4 = *(const int4*)(dst + e0);
        if ((unsigned)d4.x < (unsigned)n) atomicAdd(&g_deg[d4.x], 1);
        if ((unsigned)d4.y < (unsigned)n) atomicAdd(&g_deg[d4.y], 1);
        if ((unsigned)d4.z < (unsigned)n) atomicAdd(&g_deg[d4.z], 1);
        if ((unsigned)d4.w < (unsigned)n) atomicAdd(&g_deg[d4.w], 1);
    } else {
        for (int e = e0; e < E; e++) {
            int d = dst[e];
            if ((unsigned)d < (unsigned)n) atomicAdd(&g_deg[d], 1);
        }
    }
}

// ---------------------------------------------------------------------------
// CSR build: scan of edge counts; dinv fused into scan1.
// ---------------------------------------------------------------------------
__global__ void k_scan1(int n) {
    __shared__ int sh[SCAN_B];
    int tid = threadIdx.x;
    int i = blockIdx.x * SCAN_B + tid;
    int v = (i < n) ? g_deg[i] : 0;
    sh[tid] = v;
    __syncthreads();
    for (int off = 1; off < SCAN_B; off <<= 1) {
        int t = (tid >= off) ? sh[tid - off] : 0;
        __syncthreads();
        sh[tid] += t;
        __syncthreads();
    }
    if (i < n) {
        g_off[i] = sh[tid] - v;              // block-local exclusive
        g_dinv[i] = rsqrtf((float)(v + 1));  // +1 self loop
    }
    if (tid == SCAN_B - 1) g_part[blockIdx.x] = sh[tid];
}

__global__ void k_scan2(int nblocks) {
    __shared__ int sh[MAXBLK];
    int tid = threadIdx.x;
    int v = (tid < nblocks) ? g_part[tid] : 0;
    sh[tid] = v;
    __syncthreads();
    for (int off = 1; off < MAXBLK; off <<= 1) {
        int t = (tid >= off) ? sh[tid - off] : 0;
        __syncthreads();
        sh[tid] += t;
        __syncthreads();
    }
    if (tid < nblocks) g_partx[tid] = sh[tid] - v;  // exclusive
}

__global__ void k_scan3(int n, int E) {
    int i = blockIdx.x * blockDim.x + threadIdx.x;
    if (i < n) {
        int o = g_off[i] + g_partx[i / SCAN_B];
        g_off[i] = o;
        g_pos[i] = o;
    }
    if (i == 0) g_off[n] = E;
}

__global__ void k_bucket(const int* __restrict__ src,
                         const int* __restrict__ dst, int E, int n) {
    int e = blockIdx.x * blockDim.x + threadIdx.x;
    if (e >= E) return;
    int s = src[e], d = dst[e];
    if ((unsigned)s >= (unsigned)n || (unsigned)d >= (unsigned)n) return;
    float nrm = g_dinv[s] * g_dinv[d];
    int p = atomicAdd(&g_pos[d], 1);
    g_edge[p] = make_int2(s, __float_as_int(nrm));
}

// ---------------------------------------------------------------------------
// GEMM1 (tf32 tensor cores): g_H1[n,128] = X[n,128] @ W1[128,128], fp16 out.
// ---------------------------------------------------------------------------
__global__ void k_gemm1(const float* __restrict__ X, const float* __restrict__ W,
                        int n) {
    __shared__ float Xs[128][36];   // [row][kk]
    __shared__ float Ws[32][132];   // [kk][n]
    int tid = threadIdx.x;
    int warp = tid >> 5, lane = tid & 31;
    int rowBase = blockIdx.x * 128;
    int r0 = warp * 16;

    float c[16][4];
#pragma unroll
    for (int t = 0; t < 16; t++)
#pragma unroll
        for (int q = 0; q < 4; q++) c[t][q] = 0.f;

    for (int k0 = 0; k0 < 128; k0 += 32) {
        for (int i = tid; i < 1024; i += 256) {
            int row = i >> 3, c4 = (i & 7) * 4;
            int grow = rowBase + row;
            float4 v = make_float4(0.f, 0.f, 0.f, 0.f);
            if (grow < n) v = *(const float4*)&X[(size_t)grow * 128 + k0 + c4];
            Xs[row][c4 + 0] = to_tf32(v.x);
            Xs[row][c4 + 1] = to_tf32(v.y);
            Xs[row][c4 + 2] = to_tf32(v.z);
            Xs[row][c4 + 3] = to_tf32(v.w);
        }
        for (int i = tid; i < 1024; i += 256) {
            int k = i >> 5, n4 = (i & 31) * 4;
            float4 v = *(const float4*)&W[(size_t)(k0 + k) * 128 + n4];
            Ws[k][n4 + 0] = to_tf32(v.x);
            Ws[k][n4 + 1] = to_tf32(v.y);
            Ws[k][n4 + 2] = to_tf32(v.z);
            Ws[k][n4 + 3] = to_tf32(v.w);
        }
        __syncthreads();

        int qr = lane >> 2, qc = lane & 3;
#pragma unroll
        for (int ks = 0; ks < 32; ks += 8) {
            uint32_t a0 = __float_as_uint(Xs[r0 + qr][ks + qc]);
            uint32_t a1 = __float_as_uint(Xs[r0 + qr + 8][ks + qc]);
            uint32_t a2 = __float_as_uint(Xs[r0 + qr][ks + qc + 4]);
            uint32_t a3 = __float_as_uint(Xs[r0 + qr + 8][ks + qc + 4]);
#pragma unroll
            for (int nt = 0; nt < 16; nt++) {
                uint32_t b0 = __float_as_uint(Ws[ks + qc][nt * 8 + qr]);
                uint32_t b1 = __float_as_uint(Ws[ks + qc + 4][nt * 8 + qr]);
                asm volatile(
                    "mma.sync.aligned.m16n8k8.row.col.f32.tf32.tf32.f32 "
                    "{%0,%1,%2,%3}, {%4,%5,%6,%7}, {%8,%9}, {%0,%1,%2,%3};"
                    : "+f"(c[nt][0]), "+f"(c[nt][1]), "+f"(c[nt][2]), "+f"(c[nt][3])
                    : "r"(a0), "r"(a1), "r"(a2), "r"(a3), "r"(b0), "r"(b1));
            }
        }
        __syncthreads();
    }

    int qr = lane >> 2, qc = lane & 3;
    int row0 = rowBase + r0 + qr;
    int row1 = row0 + 8;
    __half2* H1h2 = (__half2*)g_H1;
#pragma unroll
    for (int nt = 0; nt < 16; nt++) {
        int col = nt * 8 + qc * 2;  // even
        if (row0 < n) H1h2[(size_t)row0 * 64 + (col >> 1)] = __floats2half2_rn(c[nt][0], c[nt][1]);
        if (row1 < n) H1h2[(size_t)row1 * 64 + (col >> 1)] = __floats2half2_rn(c[nt][2], c[nt][3]);
    }
}

// ---------------------------------------------------------------------------
// GEMM2 (tf32 tensor cores): g_H2[n,40] = hidden[n,128] @ W2[128,40], fp16 out.
// ---------------------------------------------------------------------------
__global__ void k_gemm2(const float* __restrict__ Hin, const float* __restrict__ W2,
                        int n) {
    __shared__ float Xs[128][36];   // [row][kk]
    __shared__ float Ws[32][44];    // [kk][col<40]
    int tid = threadIdx.x;
    int warp = tid >> 5, lane = tid & 31;
    int rowBase = blockIdx.x * 128;
    int r0 = warp * 16;

    float c[5][4];
#pragma unroll
    for (int t = 0; t < 5; t++)
#pragma unroll
        for (int q = 0; q < 4; q++) c[t][q] = 0.f;

    for (int k0 = 0; k0 < 128; k0 += 32) {
        for (int i = tid; i < 1024; i += 256) {
            int row = i >> 3, c4 = (i & 7) * 4;
            int grow = rowBase + row;
            float4 v = make_float4(0.f, 0.f, 0.f, 0.f);
            if (grow < n) v = *(const float4*)&Hin[(size_t)grow * 128 + k0 + c4];
            Xs[row][c4 + 0] = to_tf32(v.x);
            Xs[row][c4 + 1] = to_tf32(v.y);
            Xs[row][c4 + 2] = to_tf32(v.z);
            Xs[row][c4 + 3] = to_tf32(v.w);
        }
        for (int i = tid; i < 320; i += 256) {
            int k = i / 10, c4 = (i - k * 10) * 4;
            float4 v = *(const float4*)&W2[(size_t)(k0 + k) * 40 + c4];
            Ws[k][c4 + 0] = to_tf32(v.x);
            Ws[k][c4 + 1] = to_tf32(v.y);
            Ws[k][c4 + 2] = to_tf32(v.z);
            Ws[k][c4 + 3] = to_tf32(v.w);
        }
        __syncthreads();

        int qr = lane >> 2, qc = lane & 3;
#pragma unroll
        for (int ks = 0; ks < 32; ks += 8) {
            uint32_t a0 = __float_as_uint(Xs[r0 + qr][ks + qc]);
            uint32_t a1 = __float_as_uint(Xs[r0 + qr + 8][ks + qc]);
            uint32_t a2 = __float_as_uint(Xs[r0 + qr][ks + qc + 4]);
            uint32_t a3 = __float_as_uint(Xs[r0 + qr + 8][ks + qc + 4]);
#pragma unroll
            for (int nt = 0; nt < 5; nt++) {
                uint32_t b0 = __float_as_uint(Ws[ks + qc][nt * 8 + qr]);
                uint32_t b1 = __float_as_uint(Ws[ks + qc + 4][nt * 8 + qr]);
                asm volatile(
                    "mma.sync.aligned.m16n8k8.row.col.f32.tf32.tf32.f32 "
                    "{%0,%1,%2,%3}, {%4,%5,%6,%7}, {%8,%9}, {%0,%1,%2,%3};"
                    : "+f"(c[nt][0]), "+f"(c[nt][1]), "+f"(c[nt][2]), "+f"(c[nt][3])
                    : "r"(a0), "r"(a1), "r"(a2), "r"(a3), "r"(b0), "r"(b1));
            }
        }
        __syncthreads();
    }

    int qr = lane >> 2, qc = lane & 3;
    int row0 = rowBase + r0 + qr;
    int row1 = row0 + 8;
    __half2* H2h2 = (__half2*)g_H2;
#pragma unroll
    for (int nt = 0; nt < 5; nt++) {
        int col = nt * 8 + qc * 2;  // even
        if (row0 < n) H2h2[(size_t)row0 * 20 + (col >> 1)] = __floats2half2_rn(c[nt][0], c[nt][1]);
        if (row1 < n) H2h2[(size_t)row1 * 20 + (col >> 1)] = __floats2half2_rn(c[nt][2], c[nt][3]);
    }
}

// ---------------------------------------------------------------------------
// Gather layer 1: warp per dst node; lane covers 4 cols = one 8B fp16 load.
// fp32 accumulate; writes fp32 hidden to d_out.
// ---------------------------------------------------------------------------
__device__ __forceinline__ float4 h1_row4(const uint2* H1, int row, int lane) {
    uint2 u = H1[(size_t)row * 32 + lane];
    float2 f0 = __half22float2(*(__half2*)&u.x);
    float2 f1 = __half22float2(*(__half2*)&u.y);
    return make_float4(f0.x, f0.y, f1.x, f1.y);
}

__global__ void k_gather1(const float* __restrict__ b1, float* __restrict__ out,
                          int n) {
    int w = (blockIdx.x * blockDim.x + threadIdx.x) >> 5;
    int lane = threadIdx.x & 31;
    if (w >= n) return;
    int d = w;
    float dd = g_dinv[d];
    const uint2* H1 = (const uint2*)g_H1;

    float4 v = h1_row4(H1, d, lane);
    float sl = dd * dd;
    float4 acc = make_float4(v.x * sl, v.y * sl, v.z * sl, v.w * sl);
    float4 accB = make_float4(0.f, 0.f, 0.f, 0.f);

    int start = g_off[d], end = g_off[d + 1];
    for (int base = start; base < end; base += 32) {
        int idx = base + lane;
        int2 ev = (idx < end) ? g_edge[idx] : make_int2(0, 0);
        int   sv = ev.x;
        float nv = __int_as_float(ev.y);
        int cnt = end - base; if (cnt > 32) cnt = 32;
        int j = 0;
        for (; j + 1 < cnt; j += 2) {
            int   s0 = __shfl_sync(0xffffffffu, sv, j);
            int   s1 = __shfl_sync(0xffffffffu, sv, j + 1);
            float n0 = __shfl_sync(0xffffffffu, nv, j);
            float n1 = __shfl_sync(0xffffffffu, nv, j + 1);
            float4 v0 = h1_row4(H1, s0, lane);
            float4 v1 = h1_row4(H1, s1, lane);
            acc.x  = fmaf(v0.x, n0, acc.x);
            acc.y  = fmaf(v0.y, n0, acc.y);
            acc.z  = fmaf(v0.z, n0, acc.z);
            acc.w  = fmaf(v0.w, n0, acc.w);
            accB.x = fmaf(v1.x, n1, accB.x);
            accB.y = fmaf(v1.y, n1, accB.y);
            accB.z = fmaf(v1.z, n1, accB.z);
            accB.w = fmaf(v1.w, n1, accB.w);
        }
        if (j < cnt) {
            int   s0 = __shfl_sync(0xffffffffu, sv, j);
            float n0 = __shfl_sync(0xffffffffu, nv, j);
            float4 v0 = h1_row4(H1, s0, lane);
            acc.x = fmaf(v0.x, n0, acc.x);
            acc.y = fmaf(v0.y, n0, acc.y);
            acc.z = fmaf(v0.z, n0, acc.z);
            acc.w = fmaf(v0.w, n0, acc.w);
        }
    }
    acc.x += accB.x; acc.y += accB.y; acc.z += accB.z; acc.w += accB.w;

    float4 bv = ((const float4*)b1)[lane];
    acc.x = fmaxf(acc.x + bv.x, 0.f);
    acc.y = fmaxf(acc.y + bv.y, 0.f);
    acc.z = fmaxf(acc.z + bv.z, 0.f);
    acc.w = fmaxf(acc.w + bv.w, 0.f);

    ((float4*)out)[(size_t)d * 32 + lane] = acc;
}

// ---------------------------------------------------------------------------
// Gather layer 2: warp per dst; lanes 0..19 hold one half2 -> float2 (40 cols).
// ---------------------------------------------------------------------------
__global__ void k_gather2(const float* __restrict__ b2, float* __restrict__ out,
                          int n) {
    int w = (blockIdx.x * blockDim.x + threadIdx.x) >> 5;
    int lane = threadIdx.x & 31;
    if (w >= n) return;
    int d = w;
    bool act = lane < 20;
    float dd = g_dinv[d];
    const __half2* H2 = (const __half2*)g_H2;

    float2 acc = make_float2(0.f, 0.f);
    float2 accB = make_float2(0.f, 0.f);
    if (act) {
        float2 v = __half22float2(H2[(size_t)d * 20 + lane]);
        float sl = dd * dd;
        acc.x = v.x * sl; acc.y = v.y * sl;
    }

    int start = g_off[d], end = g_off[d + 1];
    for (int base = start; base < end; base += 32) {
        int idx = base + lane;
        int2 ev = (idx < end) ? g_edge[idx] : make_int2(0, 0);
        int   sv = ev.x;
        float nv = __int_as_float(ev.y);
        int cnt = end - base; if (cnt > 32) cnt = 32;
        int j = 0;
        for (; j + 1 < cnt; j += 2) {
            int   s0 = __shfl_sync(0xffffffffu, sv, j);
            int   s1 = __shfl_sync(0xffffffffu, sv, j + 1);
            float n0 = __shfl_sync(0xffffffffu, nv, j);
            float n1 = __shfl_sync(0xffffffffu, nv, j + 1);
            if (act) {
                float2 v0 = __half22float2(H2[(size_t)s0 * 20 + lane]);
                float2 v1 = __half22float2(H2[(size_t)s1 * 20 + lane]);
                acc.x  = fmaf(v0.x, n0, acc.x);
                acc.y  = fmaf(v0.y, n0, acc.y);
                accB.x = fmaf(v1.x, n1, accB.x);
                accB.y = fmaf(v1.y, n1, accB.y);
            }
        }
        if (j < cnt) {
            int   s0 = __shfl_sync(0xffffffffu, sv, j);
            float n0 = __shfl_sync(0xffffffffu, nv, j);
            if (act) {
                float2 v0 = __half22float2(H2[(size_t)s0 * 20 + lane]);
                acc.x = fmaf(v0.x, n0, acc.x);
                acc.y = fmaf(v0.y, n0, acc.y);
            }
        }
    }

    if (act) {
        acc.x += accB.x; acc.y += accB.y;
        float2 bv = ((const float2*)b2)[lane];
        acc.x += bv.x; acc.y += bv.y;
        ((float2*)out)[(size_t)d * 20 + lane] = acc;
    }
}

// ---------------------------------------------------------------------------
extern "C" void kernel_launch(void* const* d_in, const int* in_sizes, int n_in,
                              void* d_out, int out_size) {
    (void)n_in; (void)out_size;
    const float* x  = (const float*)d_in[0];
    const int*   ei = (const int*)d_in[1];     // int32 edge index
    const float* W1 = (const float*)d_in[2];
    const float* b1 = (const float*)d_in[3];
    const float* W2 = (const float*)d_in[4];
    const float* b2 = (const float*)d_in[5];

    int n = in_sizes[0] / 128;
    int E = in_sizes[1] / 2;
    const int* src = ei;
    const int* dst = ei + E;

    float* logits = (float*)d_out;                    // [n, 40]
    float* hidden = logits + (size_t)n * 40;          // [n, 128]

    const int B = 256;
    int nscan = (n + SCAN_B - 1) / SCAN_B;

    void* degPtr = nullptr;
    cudaGetSymbolAddress(&degPtr, g_deg);
    cudaMemsetAsync(degPtr, 0, (size_t)n * sizeof(int));

    k_deg_count<<<((E + 3) / 4 + B - 1) / B, B>>>(dst, E, n);
    k_scan1<<<nscan, SCAN_B>>>(n);
    k_scan2<<<1, MAXBLK>>>(nscan);
    k_scan3<<<(n + B - 1) / B, B>>>(n, E);
    k_bucket<<<(E + B - 1) / B, B>>>(src, dst, E, n);

    // Layer 1: tf32 tensor GEMM (fp16 out) then gather (bias+relu -> d_out)
    k_gemm1<<<(n + 127) / 128, B>>>(x, W1, n);
    k_gather1<<<(n * 32 + B - 1) / B, B>>>(b1, hidden, n);

    // Layer 2: tf32 tensor GEMM (fp16 out) then gather -> logits
    k_gemm2<<<(n + 127) / 128, B>>>(hidden, W2, n);
    k_gather2<<<(n * 32 + B - 1) / B, B>>>(b2, logits, n);
}

// round 14
// speedup vs baseline: 3.3421x; 1.0212x over previous
#include <cuda_runtime.h>
#include <cuda_fp16.h>
#include <cstdint>

#define NMAX 100000
#define EMAX 1600000
#define SCAN_B 1024
#define MAXBLK 128   // >= ceil(NMAX/SCAN_B) = 98

// Scratch (allocation-free rule: __device__ globals).
__device__ __half g_H1[(size_t)NMAX * 128];  // x @ W1 (fp16 storage)
__device__ __half g_H2[(size_t)NMAX * 40];   // hidden @ W2 (fp16 storage)
__device__ float g_dinv[NMAX];
__device__ int   g_deg[NMAX];                // in-degree (no self loop)
__device__ int   g_off[NMAX + 1];            // CSR row offsets (by dst)
__device__ int   g_pos[NMAX];                // bucket cursors
__device__ int2  g_edge[EMAX];               // {src, bits(nrm)} per CSR slot
__device__ int   g_part[MAXBLK];             // scan partials
__device__ int   g_partx[MAXBLK];            // exclusive-scanned partials

__device__ __forceinline__ float to_tf32(float f) {
    uint32_t u;
    asm("cvt.rna.tf32.f32 %0, %1;" : "=r"(u) : "f"(f));
    return __uint_as_float(u);
}

// ---------------------------------------------------------------------------
// Degree count, 4 edges per thread (g_deg zeroed by cudaMemsetAsync)
// ---------------------------------------------------------------------------
__global__ void k_deg_count(const int* __restrict__ dst, int E, int n) {
    int t = blockIdx.x * blockDim.x + threadIdx.x;
    int e0 = t * 4;
    if (e0 + 3 < E) {
        int4 d4 = *(const int4*)(dst + e0);
        if ((unsigned)d4.x < (unsigned)n) atomicAdd(&g_deg[d4.x], 1);
        if ((unsigned)d4.y < (unsigned)n) atomicAdd(&g_deg[d4.y], 1);
        if ((unsigned)d4.z < (unsigned)n) atomicAdd(&g_deg[d4.z], 1);
        if ((unsigned)d4.w < (unsigned)n) atomicAdd(&g_deg[d4.w], 1);
    } else {
        for (int e = e0; e < E; e++) {
            int d = dst[e];
            if ((unsigned)d < (unsigned)n) atomicAdd(&g_deg[d], 1);
        }
    }
}

// ---------------------------------------------------------------------------
// CSR build: scan of edge counts; dinv fused into scan1.
// ---------------------------------------------------------------------------
__global__ void k_scan1(int n) {
    __shared__ int sh[SCAN_B];
    int tid = threadIdx.x;
    int i = blockIdx.x * SCAN_B + tid;
    int v = (i < n) ? g_deg[i] : 0;
    sh[tid] = v;
    __syncthreads();
    for (int off = 1; off < SCAN_B; off <<= 1) {
        int t = (tid >= off) ? sh[tid - off] : 0;
        __syncthreads();
        sh[tid] += t;
        __syncthreads();
    }
    if (i < n) {
        g_off[i] = sh[tid] - v;              // block-local exclusive
        g_dinv[i] = rsqrtf((float)(v + 1));  // +1 self loop
    }
    if (tid == SCAN_B - 1) g_part[blockIdx.x] = sh[tid];
}

__global__ void k_scan2(int nblocks) {
    __shared__ int sh[MAXBLK];
    int tid = threadIdx.x;
    int v = (tid < nblocks) ? g_part[tid] : 0;
    sh[tid] = v;
    __syncthreads();
    for (int off = 1; off < MAXBLK; off <<= 1) {
        int t = (tid >= off) ? sh[tid - off] : 0;
        __syncthreads();
        sh[tid] += t;
        __syncthreads();
    }
    if (tid < nblocks) g_partx[tid] = sh[tid] - v;  // exclusive
}

__global__ void k_scan3(int n, int E) {
    int i = blockIdx.x * blockDim.x + threadIdx.x;
    if (i < n) {
        int o = g_off[i] + g_partx[i / SCAN_B];
        g_off[i] = o;
        g_pos[i] = o;
    }
    if (i == 0) g_off[n] = E;
}

__global__ void k_bucket(const int* __restrict__ src,
                         const int* __restrict__ dst, int E, int n) {
    int e = blockIdx.x * blockDim.x + threadIdx.x;
    if (e >= E) return;
    int s = src[e], d = dst[e];
    if ((unsigned)s >= (unsigned)n || (unsigned)d >= (unsigned)n) return;
    float nrm = g_dinv[s] * g_dinv[d];
    int p = atomicAdd(&g_pos[d], 1);
    g_edge[p] = make_int2(s, __float_as_int(nrm));
}

// ---------------------------------------------------------------------------
// GEMM1 (tf32 tensor cores): g_H1[n,128] = X[n,128] @ W1[128,128], fp16 out.
// ---------------------------------------------------------------------------
__global__ void k_gemm1(const float* __restrict__ X, const float* __restrict__ W,
                        int n) {
    __shared__ float Xs[128][36];   // [row][kk]
    __shared__ float Ws[32][132];   // [kk][n]
    int tid = threadIdx.x;
    int warp = tid >> 5, lane = tid & 31;
    int rowBase = blockIdx.x * 128;
    int r0 = warp * 16;

    float c[16][4];
#pragma unroll
    for (int t = 0; t < 16; t++)
#pragma unroll
        for (int q = 0; q < 4; q++) c[t][q] = 0.f;

    for (int k0 = 0; k0 < 128; k0 += 32) {
        for (int i = tid; i < 1024; i += 256) {
            int row = i >> 3, c4 = (i & 7) * 4;
            int grow = rowBase + row;
            float4 v = make_float4(0.f, 0.f, 0.f, 0.f);
            if (grow < n) v = *(const float4*)&X[(size_t)grow * 128 + k0 + c4];
            Xs[row][c4 + 0] = to_tf32(v.x);
            Xs[row][c4 + 1] = to_tf32(v.y);
            Xs[row][c4 + 2] = to_tf32(v.z);
            Xs[row][c4 + 3] = to_tf32(v.w);
        }
        for (int i = tid; i < 1024; i += 256) {
            int k = i >> 5, n4 = (i & 31) * 4;
            float4 v = *(const float4*)&W[(size_t)(k0 + k) * 128 + n4];
            Ws[k][n4 + 0] = to_tf32(v.x);
            Ws[k][n4 + 1] = to_tf32(v.y);
            Ws[k][n4 + 2] = to_tf32(v.z);
            Ws[k][n4 + 3] = to_tf32(v.w);
        }
        __syncthreads();

        int qr = lane >> 2, qc = lane & 3;
#pragma unroll
        for (int ks = 0; ks < 32; ks += 8) {
            uint32_t a0 = __float_as_uint(Xs[r0 + qr][ks + qc]);
            uint32_t a1 = __float_as_uint(Xs[r0 + qr + 8][ks + qc]);
            uint32_t a2 = __float_as_uint(Xs[r0 + qr][ks + qc + 4]);
            uint32_t a3 = __float_as_uint(Xs[r0 + qr + 8][ks + qc + 4]);
#pragma unroll
            for (int nt = 0; nt < 16; nt++) {
                uint32_t b0 = __float_as_uint(Ws[ks + qc][nt * 8 + qr]);
                uint32_t b1 = __float_as_uint(Ws[ks + qc + 4][nt * 8 + qr]);
                asm volatile(
                    "mma.sync.aligned.m16n8k8.row.col.f32.tf32.tf32.f32 "
                    "{%0,%1,%2,%3}, {%4,%5,%6,%7}, {%8,%9}, {%0,%1,%2,%3};"
                    : "+f"(c[nt][0]), "+f"(c[nt][1]), "+f"(c[nt][2]), "+f"(c[nt][3])
                    : "r"(a0), "r"(a1), "r"(a2), "r"(a3), "r"(b0), "r"(b1));
            }
        }
        __syncthreads();
    }

    int qr = lane >> 2, qc = lane & 3;
    int row0 = rowBase + r0 + qr;
    int row1 = row0 + 8;
    __half2* H1h2 = (__half2*)g_H1;
#pragma unroll
    for (int nt = 0; nt < 16; nt++) {
        int col = nt * 8 + qc * 2;  // even
        if (row0 < n) H1h2[(size_t)row0 * 64 + (col >> 1)] = __floats2half2_rn(c[nt][0], c[nt][1]);
        if (row1 < n) H1h2[(size_t)row1 * 64 + (col >> 1)] = __floats2half2_rn(c[nt][2], c[nt][3]);
    }
}

// ---------------------------------------------------------------------------
// GEMM2 (tf32 tensor cores): g_H2[n,40] = hidden[n,128] @ W2[128,40], fp16 out.
// ---------------------------------------------------------------------------
__global__ void k_gemm2(const float* __restrict__ Hin, const float* __restrict__ W2,
                        int n) {
    __shared__ float Xs[128][36];   // [row][kk]
    __shared__ float Ws[32][44];    // [kk][col<40]
    int tid = threadIdx.x;
    int warp = tid >> 5, lane = tid & 31;
    int rowBase = blockIdx.x * 128;
    int r0 = warp * 16;

    float c[5][4];
#pragma unroll
    for (int t = 0; t < 5; t++)
#pragma unroll
        for (int q = 0; q < 4; q++) c[t][q] = 0.f;

    for (int k0 = 0; k0 < 128; k0 += 32) {
        for (int i = tid; i < 1024; i += 256) {
            int row = i >> 3, c4 = (i & 7) * 4;
            int grow = rowBase + row;
            float4 v = make_float4(0.f, 0.f, 0.f, 0.f);
            if (grow < n) v = *(const float4*)&Hin[(size_t)grow * 128 + k0 + c4];
            Xs[row][c4 + 0] = to_tf32(v.x);
            Xs[row][c4 + 1] = to_tf32(v.y);
            Xs[row][c4 + 2] = to_tf32(v.z);
            Xs[row][c4 + 3] = to_tf32(v.w);
        }
        for (int i = tid; i < 320; i += 256) {
            int k = i / 10, c4 = (i - k * 10) * 4;
            float4 v = *(const float4*)&W2[(size_t)(k0 + k) * 40 + c4];
            Ws[k][c4 + 0] = to_tf32(v.x);
            Ws[k][c4 + 1] = to_tf32(v.y);
            Ws[k][c4 + 2] = to_tf32(v.z);
            Ws[k][c4 + 3] = to_tf32(v.w);
        }
        __syncthreads();

        int qr = lane >> 2, qc = lane & 3;
#pragma unroll
        for (int ks = 0; ks < 32; ks += 8) {
            uint32_t a0 = __float_as_uint(Xs[r0 + qr][ks + qc]);
            uint32_t a1 = __float_as_uint(Xs[r0 + qr + 8][ks + qc]);
            uint32_t a2 = __float_as_uint(Xs[r0 + qr][ks + qc + 4]);
            uint32_t a3 = __float_as_uint(Xs[r0 + qr + 8][ks + qc + 4]);
#pragma unroll
            for (int nt = 0; nt < 5; nt++) {
                uint32_t b0 = __float_as_uint(Ws[ks + qc][nt * 8 + qr]);
                uint32_t b1 = __float_as_uint(Ws[ks + qc + 4][nt * 8 + qr]);
                asm volatile(
                    "mma.sync.aligned.m16n8k8.row.col.f32.tf32.tf32.f32 "
                    "{%0,%1,%2,%3}, {%4,%5,%6,%7}, {%8,%9}, {%0,%1,%2,%3};"
                    : "+f"(c[nt][0]), "+f"(c[nt][1]), "+f"(c[nt][2]), "+f"(c[nt][3])
                    : "r"(a0), "r"(a1), "r"(a2), "r"(a3), "r"(b0), "r"(b1));
            }
        }
        __syncthreads();
    }

    int qr = lane >> 2, qc = lane & 3;
    int row0 = rowBase + r0 + qr;
    int row1 = row0 + 8;
    __half2* H2h2 = (__half2*)g_H2;
#pragma unroll
    for (int nt = 0; nt < 5; nt++) {
        int col = nt * 8 + qc * 2;  // even
        if (row0 < n) H2h2[(size_t)row0 * 20 + (col >> 1)] = __floats2half2_rn(c[nt][0], c[nt][1]);
        if (row1 < n) H2h2[(size_t)row1 * 20 + (col >> 1)] = __floats2half2_rn(c[nt][2], c[nt][3]);
    }
}

// ---------------------------------------------------------------------------
// Gather layer 1: warp per dst node; 4 independent accumulator chains (MLP=4).
// ---------------------------------------------------------------------------
__device__ __forceinline__ float4 h1_row4(const uint2* H1, int row, int lane) {
    uint2 u = H1[(size_t)row * 32 + lane];
    float2 f0 = __half22float2(*(__half2*)&u.x);
    float2 f1 = __half22float2(*(__half2*)&u.y);
    return make_float4(f0.x, f0.y, f1.x, f1.y);
}

__device__ __forceinline__ void fma4(float4& a, float4 v, float nz) {
    a.x = fmaf(v.x, nz, a.x);
    a.y = fmaf(v.y, nz, a.y);
    a.z = fmaf(v.z, nz, a.z);
    a.w = fmaf(v.w, nz, a.w);
}

__global__ void k_gather1(const float* __restrict__ b1, float* __restrict__ out,
                          int n) {
    int w = (blockIdx.x * blockDim.x + threadIdx.x) >> 5;
    int lane = threadIdx.x & 31;
    if (w >= n) return;
    int d = w;
    float dd = g_dinv[d];
    const uint2* H1 = (const uint2*)g_H1;

    float4 v = h1_row4(H1, d, lane);
    float sl = dd * dd;
    float4 a0 = make_float4(v.x * sl, v.y * sl, v.z * sl, v.w * sl);
    float4 a1 = make_float4(0.f, 0.f, 0.f, 0.f);
    float4 a2 = make_float4(0.f, 0.f, 0.f, 0.f);
    float4 a3 = make_float4(0.f, 0.f, 0.f, 0.f);

    int start = g_off[d], end = g_off[d + 1];
    for (int base = start; base < end; base += 32) {
        int idx = base + lane;
        int2 ev = (idx < end) ? g_edge[idx] : make_int2(0, 0);
        int   sv = ev.x;
        float nv = __int_as_float(ev.y);
        int cnt = end - base; if (cnt > 32) cnt = 32;
        int j = 0;
        for (; j + 3 < cnt; j += 4) {
            int   s0 = __shfl_sync(0xffffffffu, sv, j);
            int   s1 = __shfl_sync(0xffffffffu, sv, j + 1);
            int   s2 = __shfl_sync(0xffffffffu, sv, j + 2);
            int   s3 = __shfl_sync(0xffffffffu, sv, j + 3);
            float n0 = __shfl_sync(0xffffffffu, nv, j);
            float n1 = __shfl_sync(0xffffffffu, nv, j + 1);
            float n2 = __shfl_sync(0xffffffffu, nv, j + 2);
            float n3 = __shfl_sync(0xffffffffu, nv, j + 3);
            float4 v0 = h1_row4(H1, s0, lane);
            float4 v1 = h1_row4(H1, s1, lane);
            float4 v2 = h1_row4(H1, s2, lane);
            float4 v3 = h1_row4(H1, s3, lane);
            fma4(a0, v0, n0);
            fma4(a1, v1, n1);
            fma4(a2, v2, n2);
            fma4(a3, v3, n3);
        }
        for (; j < cnt; j++) {
            int   s0 = __shfl_sync(0xffffffffu, sv, j);
            float n0 = __shfl_sync(0xffffffffu, nv, j);
            float4 v0 = h1_row4(H1, s0, lane);
            fma4(a0, v0, n0);
        }
    }
    a0.x += a1.x + a2.x + a3.x;
    a0.y += a1.y + a2.y + a3.y;
    a0.z += a1.z + a2.z + a3.z;
    a0.w += a1.w + a2.w + a3.w;

    float4 bv = ((const float4*)b1)[lane];
    a0.x = fmaxf(a0.x + bv.x, 0.f);
    a0.y = fmaxf(a0.y + bv.y, 0.f);
    a0.z = fmaxf(a0.z + bv.z, 0.f);
    a0.w = fmaxf(a0.w + bv.w, 0.f);

    ((float4*)out)[(size_t)d * 32 + lane] = a0;
}

// ---------------------------------------------------------------------------
// Gather layer 2: warp per dst; lanes 0..19 hold one half2 -> float2 (40 cols).
// ---------------------------------------------------------------------------
__global__ void k_gather2(const float* __restrict__ b2, float* __restrict__ out,
                          int n) {
    int w = (blockIdx.x * blockDim.x + threadIdx.x) >> 5;
    int lane = threadIdx.x & 31;
    if (w >= n) return;
    int d = w;
    bool act = lane < 20;
    float dd = g_dinv[d];
    const __half2* H2 = (const __half2*)g_H2;

    float2 acc = make_float2(0.f, 0.f);
    float2 accB = make_float2(0.f, 0.f);
    if (act) {
        float2 v = __half22float2(H2[(size_t)d * 20 + lane]);
        float sl = dd * dd;
        acc.x = v.x * sl; acc.y = v.y * sl;
    }

    int start = g_off[d], end = g_off[d + 1];
    for (int base = start; base < end; base += 32) {
        int idx = base + lane;
        int2 ev = (idx < end) ? g_edge[idx] : make_int2(0, 0);
        int   sv = ev.x;
        float nv = __int_as_float(ev.y);
        int cnt = end - base; if (cnt > 32) cnt = 32;
        int j = 0;
        for (; j + 1 < cnt; j += 2) {
            int   s0 = __shfl_sync(0xffffffffu, sv, j);
            int   s1 = __shfl_sync(0xffffffffu, sv, j + 1);
            float n0 = __shfl_sync(0xffffffffu, nv, j);
            float n1 = __shfl_sync(0xffffffffu, nv, j + 1);
            if (act) {
                float2 v0 = __half22float2(H2[(size_t)s0 * 20 + lane]);
                float2 v1 = __half22float2(H2[(size_t)s1 * 20 + lane]);
                acc.x  = fmaf(v0.x, n0, acc.x);
                acc.y  = fmaf(v0.y, n0, acc.y);
                accB.x = fmaf(v1.x, n1, accB.x);
                accB.y = fmaf(v1.y, n1, accB.y);
            }
        }
        if (j < cnt) {
            int   s0 = __shfl_sync(0xffffffffu, sv, j);
            float n0 = __shfl_sync(0xffffffffu, nv, j);
            if (act) {
                float2 v0 = __half22float2(H2[(size_t)s0 * 20 + lane]);
                acc.x = fmaf(v0.x, n0, acc.x);
                acc.y = fmaf(v0.y, n0, acc.y);
            }
        }
    }

    if (act) {
        acc.x += accB.x; acc.y += accB.y;
        float2 bv = ((const float2*)b2)[lane];
        acc.x += bv.x; acc.y += bv.y;
        ((float2*)out)[(size_t)d * 20 + lane] = acc;
    }
}

// ---------------------------------------------------------------------------
extern "C" void kernel_launch(void* const* d_in, const int* in_sizes, int n_in,
                              void* d_out, int out_size) {
    (void)n_in; (void)out_size;
    const float* x  = (const float*)d_in[0];
    const int*   ei = (const int*)d_in[1];     // int32 edge index
    const float* W1 = (const float*)d_in[2];
    const float* b1 = (const float*)d_in[3];
    const float* W2 = (const float*)d_in[4];
    const float* b2 = (const float*)d_in[5];

    int n = in_sizes[0] / 128;
    int E = in_sizes[1] / 2;
    const int* src = ei;
    const int* dst = ei + E;

    float* logits = (float*)d_out;                    // [n, 40]
    float* hidden = logits + (size_t)n * 40;          // [n, 128]

    const int B = 256;
    int nscan = (n + SCAN_B - 1) / SCAN_B;

    void* degPtr = nullptr;
    cudaGetSymbolAddress(&degPtr, g_deg);

    // Fork: gemm1 (side stream) overlaps the CSR build (main stream).
    cudaStream_t s1;
    cudaStreamCreateWithFlags(&s1, cudaStreamNonBlocking);
    cudaEvent_t evFork, evJoin;
    cudaEventCreateWithFlags(&evFork, cudaEventDisableTiming);
    cudaEventCreateWithFlags(&evJoin, cudaEventDisableTiming);

    cudaEventRecord(evFork, 0);
    cudaStreamWaitEvent(s1, evFork, 0);
    k_gemm1<<<(n + 127) / 128, B, 0, s1>>>(x, W1, n);
    cudaEventRecord(evJoin, s1);

    // Main stream: CSR build
    cudaMemsetAsync(degPtr, 0, (size_t)n * sizeof(int));
    k_deg_count<<<((E + 3) / 4 + B - 1) / B, B>>>(dst, E, n);
    k_scan1<<<nscan, SCAN_B>>>(n);
    k_scan2<<<1, MAXBLK>>>(nscan);
    k_scan3<<<(n + B - 1) / B, B>>>(n, E);
    k_bucket<<<(E + B - 1) / B, B>>>(src, dst, E, n);

    // Join, then gather1 (needs both CSR and g_H1)
    cudaStreamWaitEvent(0, evJoin, 0);
    k_gather1<<<(n * 32 + B - 1) / B, B>>>(b1, hidden, n);

    // Layer 2: tf32 tensor GEMM (fp16 out) then gather -> logits
    k_gemm2<<<(n + 127) / 128, B>>>(hidden, W2, n);
    k_gather2<<<(n * 32 + B - 1) / B, B>>>(b2, logits, n);

    // Release per-call resources (host-side objects; safe under capture)
    cudaEventDestroy(evFork);
    cudaEventDestroy(evJoin);
    cudaStreamDestroy(s1);
}